// round 1
// baseline (speedup 1.0000x reference)
#include <cuda_runtime.h>
#include <math.h>

// Problem constants
#define B_ 8
#define N_ 4096
#define C_ 512
#define H_ 8
#define P_ 64
#define D_ 64

// ---------------- scratch (device globals; no runtime allocation) ----------------
__device__ float g_qkv[B_ * N_ * 3 * C_];      // [b, n, 1536]  (q|k|v, head-interleaved)
__device__ float g_qinv[B_ * H_ * D_];         // 1/||q||_2 over tokens per (b,h,d)
__device__ float g_kp[B_ * H_ * P_ * D_];      // [b,h,p,d]
__device__ float g_vp[B_ * H_ * P_ * D_];      // [b,h,p,d]
__device__ float g_gram[B_ * C_ * C_];         // channel-attn scores, softmaxed in place
__device__ float g_Mmat[B_ * C_ * (C_ / 2)];   // folded attn^T @ w_o2^T  [b, c', j]
__device__ float g_xsa[B_ * N_ * C_];          // scrambled x_sa ready for w_o1 GEMM

// ---------------- shared 4x4 microtile FMA ----------------
__device__ __forceinline__ void fma44(float (&acc)[4][4], const float* Ar,
                                      const float* Br, int ty, int tx) {
    float4 a4 = *(const float4*)(Ar + ty * 4);
    float4 b4 = *(const float4*)(Br + tx * 4);
    float a[4] = {a4.x, a4.y, a4.z, a4.w};
    float b[4] = {b4.x, b4.y, b4.z, b4.w};
#pragma unroll
    for (int i = 0; i < 4; i++)
#pragma unroll
        for (int j = 0; j < 4; j++) acc[i][j] += a[i] * b[j];
}

// Padded smem row stride: 68 floats = 272B (16B aligned rows, STS conflicts <= 2-way)
#define SP 68

// ================= K1: qkv = x @ w_qkv^T  (M=32768, N=1536, K=512, NT) =================
__global__ __launch_bounds__(256) void k_qkv(const float* __restrict__ x,
                                             const float* __restrict__ w) {
    __shared__ float As[16][SP];
    __shared__ float Bs[16][SP];
    int tid = threadIdx.x;
    int m0 = blockIdx.y * 64;
    int n0 = blockIdx.x * 64;
    int lk = tid & 15, lr = tid >> 4;
    int tx = tid & 15, ty = tid >> 4;
    float acc[4][4] = {};
    for (int k0 = 0; k0 < 512; k0 += 16) {
#pragma unroll
        for (int u = 0; u < 4; u++) {
            int r = lr + 16 * u;
            As[lk][r] = x[(m0 + r) * 512 + k0 + lk];
            Bs[lk][r] = w[(n0 + r) * 512 + k0 + lk];
        }
        __syncthreads();
#pragma unroll
        for (int kk = 0; kk < 16; kk++) fma44(acc, As[kk], Bs[kk], ty, tx);
        __syncthreads();
    }
#pragma unroll
    for (int i = 0; i < 4; i++) {
        float4 v = make_float4(acc[i][0], acc[i][1], acc[i][2], acc[i][3]);
        *(float4*)&g_qkv[(m0 + ty * 4 + i) * 1536 + n0 + tx * 4] = v;
    }
}

// ================= K2: q token-axis L2 norm inverses =================
__global__ __launch_bounds__(256) void k_qnorm() {
    int bh = blockIdx.x;
    int b = bh >> 3, h = bh & 7;
    int tid = threadIdx.x;
    int d = tid & 63, sl = tid >> 6;
    const float* q = g_qkv + b * (N_ * 1536) + h * 64 + d;
    float s = 0.f;
    for (int n = sl; n < N_; n += 4) {
        float v = q[n * 1536];
        s += v * v;
    }
    __shared__ float red[256];
    red[tid] = s;
    __syncthreads();
    if (sl == 0) {
        float tot = red[d] + red[d + 64] + red[d + 128] + red[d + 192];
        g_qinv[bh * 64 + d] = 1.f / fmaxf(sqrtf(tot), 1e-12f);
    }
}

// ================= K3: kp/vp[p,d] = sum_n w_e[p,n]*K(V)[n,d] + b_e[p] =================
__global__ __launch_bounds__(256) void k_proj(const float* __restrict__ w_e,
                                              const float* __restrict__ b_e) {
    __shared__ float As[16][SP];  // [kk][p]
    __shared__ float Bs[16][SP];  // [kk][d]
    int bh = blockIdx.x, kv = blockIdx.y;  // kv: 0=k, 1=v
    int b = bh >> 3, h = bh & 7;
    const float* src = g_qkv + b * (N_ * 1536) + 512 * (1 + kv) + h * 64;
    int tid = threadIdx.x;
    int tx = tid & 15, ty = tid >> 4;
    int lkA = tid & 15, lpA = tid >> 4;
    int ldB = tid & 63, lkB = tid >> 6;
    float acc[4][4] = {};
    for (int n0 = 0; n0 < N_; n0 += 16) {
#pragma unroll
        for (int u = 0; u < 4; u++) {
            int p = lpA + 16 * u;
            As[lkA][p] = w_e[p * N_ + n0 + lkA];
            int kk = lkB + 4 * u;
            Bs[kk][ldB] = src[(n0 + kk) * 1536 + ldB];
        }
        __syncthreads();
#pragma unroll
        for (int kk = 0; kk < 16; kk++) fma44(acc, As[kk], Bs[kk], ty, tx);
        __syncthreads();
    }
    float* dst = (kv ? g_vp : g_kp) + bh * (P_ * D_);
#pragma unroll
    for (int i = 0; i < 4; i++) {
        int p = ty * 4 + i;
        float be = b_e[p];
        float4 v = make_float4(acc[i][0] + be, acc[i][1] + be, acc[i][2] + be,
                               acc[i][3] + be);
        *(float4*)&dst[p * 64 + tx * 4] = v;
    }
}

// ================= K4: Gram[b] = X^T X  (512x512, K=4096) =================
__global__ __launch_bounds__(256) void k_gram(const float* __restrict__ x) {
    __shared__ float As[16][SP];
    __shared__ float Bs[16][SP];
    int b = blockIdx.z;
    int c10 = blockIdx.y * 64, c20 = blockIdx.x * 64;
    const float* xb = x + b * (N_ * C_);
    int tid = threadIdx.x;
    int tx = tid & 15, ty = tid >> 4;
    int lm = tid & 63, lk = tid >> 6;
    float acc[4][4] = {};
    for (int k0 = 0; k0 < N_; k0 += 16) {
#pragma unroll
        for (int u = 0; u < 4; u++) {
            int kk = lk + 4 * u;
            As[kk][lm] = xb[(k0 + kk) * 512 + c10 + lm];
            Bs[kk][lm] = xb[(k0 + kk) * 512 + c20 + lm];
        }
        __syncthreads();
#pragma unroll
        for (int kk = 0; kk < 16; kk++) fma44(acc, As[kk], Bs[kk], ty, tx);
        __syncthreads();
    }
#pragma unroll
    for (int i = 0; i < 4; i++) {
        float4 v = make_float4(acc[i][0], acc[i][1], acc[i][2], acc[i][3]);
        *(float4*)&g_gram[(b * 512 + c10 + ty * 4 + i) * 512 + c20 + tx * 4] = v;
    }
}

// ================= K5: row softmax of Gram * temperature (in place) =================
__global__ __launch_bounds__(256) void k_softmax512(const float* __restrict__ temp) {
    int row = blockIdx.x;
    float t = temp[0];
    float* p = g_gram + row * 512;
    int tid = threadIdx.x;
    __shared__ float red[256];
    float v0 = p[tid] * t, v1 = p[tid + 256] * t;
    red[tid] = fmaxf(v0, v1);
    __syncthreads();
    for (int s = 128; s > 0; s >>= 1) {
        if (tid < s) red[tid] = fmaxf(red[tid], red[tid + s]);
        __syncthreads();
    }
    float mx = red[0];
    __syncthreads();
    float e0 = __expf(v0 - mx), e1 = __expf(v1 - mx);
    red[tid] = e0 + e1;
    __syncthreads();
    for (int s = 128; s > 0; s >>= 1) {
        if (tid < s) red[tid] += red[tid + s];
        __syncthreads();
    }
    float inv = 1.f / red[0];
    p[tid] = e0 * inv;
    p[tid + 256] = e1 * inv;
}

// ================= K6: fused spatial attention + permute scramble =================
__global__ __launch_bounds__(128) void k_sa(const float* __restrict__ temp2) {
    __shared__ float kp_s[P_ * D_];
    __shared__ float vp_s[P_ * D_];
    __shared__ float qi_s[D_];
    int bh = blockIdx.y;
    int b = bh >> 3, h = bh & 7;
    int n = blockIdx.x * 128 + threadIdx.x;
    const float4* kp4 = (const float4*)(g_kp + bh * (P_ * D_));
    const float4* vp4 = (const float4*)(g_vp + bh * (P_ * D_));
    for (int i = threadIdx.x; i < (P_ * D_) / 4; i += 128) {
        ((float4*)kp_s)[i] = kp4[i];
        ((float4*)vp_s)[i] = vp4[i];
    }
    if (threadIdx.x < 64) qi_s[threadIdx.x] = g_qinv[bh * 64 + threadIdx.x];
    __syncthreads();
    float t2 = temp2[h];
    const float* qrow = g_qkv + b * (N_ * 1536) + n * 1536 + h * 64;

    float q[64];
#pragma unroll
    for (int d = 0; d < 64; d++) q[d] = qrow[d] * qi_s[d];

    float s[64];
    float mx = -1e30f;
#pragma unroll
    for (int p = 0; p < 64; p++) {
        float acc = 0.f;
#pragma unroll
        for (int d = 0; d < 64; d += 4) {
            float4 k4 = *(const float4*)&kp_s[p * 64 + d];
            acc += q[d] * k4.x + q[d + 1] * k4.y + q[d + 2] * k4.z + q[d + 3] * k4.w;
        }
        s[p] = acc * t2;
        mx = fmaxf(mx, s[p]);
    }
    float sum = 0.f;
#pragma unroll
    for (int p = 0; p < 64; p++) {
        s[p] = __expf(s[p] - mx);
        sum += s[p];
    }
    float inv = 1.f / sum;

    float o[64];
#pragma unroll
    for (int d = 0; d < 64; d++) o[d] = 0.f;
#pragma unroll
    for (int p = 0; p < 64; p++) {
        float sp = s[p] * inv;
#pragma unroll
        for (int d = 0; d < 64; d += 4) {
            float4 v4 = *(const float4*)&vp_s[p * 64 + d];
            o[d] += sp * v4.x;
            o[d + 1] += sp * v4.y;
            o[d + 2] += sp * v4.z;
            o[d + 3] += sp * v4.w;
        }
    }
    // faithful permute(0,3,1,2).reshape: row = d*64 + h*8 + (n>>9), col = n&511
    int rbase = h * 8 + (n >> 9);
    int col = n & 511;
    float* xsa = g_xsa + b * (N_ * C_);
#pragma unroll
    for (int d = 0; d < 64; d++) xsa[(d * 64 + rbase) * 512 + col] = o[d];
}

// ================= K7: M[b] = attn^T @ w_o2^T  (512 x 256, K=512) =================
__global__ __launch_bounds__(256) void k_M(const float* __restrict__ w_o2) {
    __shared__ float As[16][SP];  // [kk][c']
    __shared__ float Bs[16][SP];  // [kk][j]
    int b = blockIdx.z;
    int m0 = blockIdx.y * 64;  // c'
    int n0 = blockIdx.x * 64;  // j
    const float* A = g_gram + b * (512 * 512);
    int tid = threadIdx.x;
    int tx = tid & 15, ty = tid >> 4;
    int lm = tid & 63, lkA = tid >> 6;
    int lkB = tid & 15, ljB = tid >> 4;
    float acc[4][4] = {};
    for (int k0 = 0; k0 < 512; k0 += 16) {
#pragma unroll
        for (int u = 0; u < 4; u++) {
            int kk = lkA + 4 * u;
            As[kk][lm] = A[(k0 + kk) * 512 + m0 + lm];
            int j = ljB + 16 * u;
            Bs[lkB][j] = w_o2[(n0 + j) * 512 + k0 + lkB];
        }
        __syncthreads();
#pragma unroll
        for (int kk = 0; kk < 16; kk++) fma44(acc, As[kk], Bs[kk], ty, tx);
        __syncthreads();
    }
#pragma unroll
    for (int i = 0; i < 4; i++) {
        float4 v = make_float4(acc[i][0], acc[i][1], acc[i][2], acc[i][3]);
        *(float4*)&g_Mmat[(b * 512 + m0 + ty * 4 + i) * 256 + n0 + tx * 4] = v;
    }
}

// ================= K8: out[:, :256] = xsa_scrambled @ w_o1^T + b_o1 =================
__global__ __launch_bounds__(256) void k_out1(const float* __restrict__ w_o1,
                                              const float* __restrict__ b_o1,
                                              float* __restrict__ out) {
    __shared__ float As[16][SP];
    __shared__ float Bs[16][SP];
    int m0 = blockIdx.y * 64;
    int n0 = blockIdx.x * 64;
    int tid = threadIdx.x;
    int tx = tid & 15, ty = tid >> 4;
    int lk = tid & 15, lr = tid >> 4;
    float acc[4][4] = {};
    for (int k0 = 0; k0 < 512; k0 += 16) {
#pragma unroll
        for (int u = 0; u < 4; u++) {
            int r = lr + 16 * u;
            As[lk][r] = g_xsa[(m0 + r) * 512 + k0 + lk];
            Bs[lk][r] = w_o1[(n0 + r) * 512 + k0 + lk];
        }
        __syncthreads();
#pragma unroll
        for (int kk = 0; kk < 16; kk++) fma44(acc, As[kk], Bs[kk], ty, tx);
        __syncthreads();
    }
#pragma unroll
    for (int i = 0; i < 4; i++) {
        int j0 = n0 + tx * 4;
        float4 v = make_float4(acc[i][0] + b_o1[j0], acc[i][1] + b_o1[j0 + 1],
                               acc[i][2] + b_o1[j0 + 2], acc[i][3] + b_o1[j0 + 3]);
        *(float4*)&out[(m0 + ty * 4 + i) * 512 + j0] = v;
    }
}

// ================= K9: out[:, 256:] = x @ M[b] + b_o2 =================
__global__ __launch_bounds__(256) void k_out2(const float* __restrict__ x,
                                              const float* __restrict__ b_o2,
                                              float* __restrict__ out) {
    __shared__ float As[16][SP];
    __shared__ float Bs[16][SP];
    int m0 = blockIdx.y * 64;
    int n0 = blockIdx.x * 64;
    int b = m0 >> 12;  // 4096 rows per batch
    const float* Bm = g_Mmat + b * (512 * 256);
    int tid = threadIdx.x;
    int tx = tid & 15, ty = tid >> 4;
    int lkA = tid & 15, lrA = tid >> 4;
    int ljB = tid & 63, lkB = tid >> 6;
    float acc[4][4] = {};
    for (int k0 = 0; k0 < 512; k0 += 16) {
#pragma unroll
        for (int u = 0; u < 4; u++) {
            int r = lrA + 16 * u;
            As[lkA][r] = x[(m0 + r) * 512 + k0 + lkA];
            int kk = lkB + 4 * u;
            Bs[kk][ljB] = Bm[(k0 + kk) * 256 + n0 + ljB];
        }
        __syncthreads();
#pragma unroll
        for (int kk = 0; kk < 16; kk++) fma44(acc, As[kk], Bs[kk], ty, tx);
        __syncthreads();
    }
#pragma unroll
    for (int i = 0; i < 4; i++) {
        int j0 = n0 + tx * 4;
        float4 v = make_float4(acc[i][0] + b_o2[j0], acc[i][1] + b_o2[j0 + 1],
                               acc[i][2] + b_o2[j0 + 2], acc[i][3] + b_o2[j0 + 3]);
        *(float4*)&out[(m0 + ty * 4 + i) * 512 + 256 + j0] = v;
    }
}

// ================= launch =================
extern "C" void kernel_launch(void* const* d_in, const int* in_sizes, int n_in,
                              void* d_out, int out_size) {
    const float* x      = (const float*)d_in[0];
    const float* w_qkv  = (const float*)d_in[1];
    const float* w_e    = (const float*)d_in[2];
    const float* b_e    = (const float*)d_in[3];
    const float* temp   = (const float*)d_in[4];
    const float* temp2  = (const float*)d_in[5];
    const float* w_o1   = (const float*)d_in[6];
    const float* b_o1   = (const float*)d_in[7];
    const float* w_o2   = (const float*)d_in[8];
    const float* b_o2   = (const float*)d_in[9];
    float* out = (float*)d_out;

    k_qkv<<<dim3(24, 512), 256>>>(x, w_qkv);          // 51.5 GF
    k_qnorm<<<64, 256>>>();                           // reductions
    k_proj<<<dim3(64, 2), 256>>>(w_e, b_e);           // 8.6 GF
    k_gram<<<dim3(8, 8, 8), 256>>>(x);                // 17.2 GF
    k_softmax512<<<B_ * C_, 256>>>(temp);             // in-place
    k_sa<<<dim3(32, 64), 128>>>(temp2);               // 8.6 GF fused
    k_M<<<dim3(4, 8, 8), 256>>>(w_o2);                // 1.1 GF (fusion)
    k_out1<<<dim3(4, 512), 256>>>(w_o1, b_o1, out);   // 8.6 GF
    k_out2<<<dim3(4, 512), 256>>>(x, b_o2, out);      // 8.6 GF
}

// round 2
// speedup vs baseline: 1.0968x; 1.0968x over previous
#include <cuda_runtime.h>
#include <math.h>

// Problem constants
#define B_ 8
#define N_ 4096
#define C_ 512
#define H_ 8
#define P_ 64
#define D_ 64

// ---------------- scratch (device globals; no runtime allocation) ----------------
__device__ float g_qkv[B_ * N_ * 3 * C_];      // [b, n, 1536]  (q|k|v, head-interleaved)
__device__ float g_qinv[B_ * H_ * D_];         // 1/||q||_2 over tokens per (b,h,d)
__device__ float g_kp[B_ * H_ * P_ * D_];      // [b,h,p,d]
__device__ float g_vp[B_ * H_ * P_ * D_];      // [b,h,p,d]
__device__ float g_gram[B_ * C_ * C_];         // channel-attn scores, softmaxed in place
__device__ float g_Mmat[B_ * C_ * (C_ / 2)];   // folded attn^T @ w_o2^T  [b, c', j]
__device__ float g_xsa[B_ * N_ * C_];          // scrambled x_sa ready for w_o1 GEMM

// =====================================================================
// 128x128 block / 8x8 microtile / BK=8 double-buffered SGEMM core.
// AT=true : global A is [M,K] row-major (transpose-on-store to smem)
// AT=false: global A is [K,M] row-major (direct coalesced store)
// Same for BT with N in place of M. A/B passed pre-offset to tile origin.
// =====================================================================
#define SP2 132   // padded smem row: kills transpose-store bank conflicts

template <bool AT, bool BT>
__device__ __forceinline__ void gemm128x128(
    const float* __restrict__ A, int lda,
    const float* __restrict__ B, int ldb,
    int K, float (&acc)[8][8],
    float (*As)[8][SP2], float (*Bs)[8][SP2]) {
    int tid = threadIdx.x;
    int tx = tid & 15, ty = tid >> 4;

    int rowT = tid >> 1;          // transpose-path row (0..127)
    int kqT = (tid & 1) * 4;      // transpose-path k offset
    int krD = tid >> 5;           // direct-path k row (0..7)
    int mqD = (tid & 31) * 4;     // direct-path col offset

    float4 ra, rb;

    auto loadA = [&](int k0) {
        if (AT) ra = *(const float4*)&A[rowT * lda + k0 + kqT];
        else    ra = *(const float4*)&A[(k0 + krD) * lda + mqD];
    };
    auto loadB = [&](int k0) {
        if (BT) rb = *(const float4*)&B[rowT * ldb + k0 + kqT];
        else    rb = *(const float4*)&B[(k0 + krD) * ldb + mqD];
    };
    auto storeA = [&](int buf) {
        if (AT) {
            As[buf][kqT + 0][rowT] = ra.x; As[buf][kqT + 1][rowT] = ra.y;
            As[buf][kqT + 2][rowT] = ra.z; As[buf][kqT + 3][rowT] = ra.w;
        } else {
            *(float4*)&As[buf][krD][mqD] = ra;
        }
    };
    auto storeB = [&](int buf) {
        if (BT) {
            Bs[buf][kqT + 0][rowT] = rb.x; Bs[buf][kqT + 1][rowT] = rb.y;
            Bs[buf][kqT + 2][rowT] = rb.z; Bs[buf][kqT + 3][rowT] = rb.w;
        } else {
            *(float4*)&Bs[buf][krD][mqD] = rb;
        }
    };

    loadA(0); loadB(0);
    storeA(0); storeB(0);
    __syncthreads();

    int nk = K >> 3;
    for (int kt = 0; kt < nk; kt++) {
        int cur = kt & 1;
        if (kt + 1 < nk) { loadA((kt + 1) << 3); loadB((kt + 1) << 3); }
#pragma unroll
        for (int kk = 0; kk < 8; kk++) {
            float4 a0 = *(const float4*)&As[cur][kk][ty * 8];
            float4 a1 = *(const float4*)&As[cur][kk][ty * 8 + 4];
            float4 b0 = *(const float4*)&Bs[cur][kk][tx * 8];
            float4 b1 = *(const float4*)&Bs[cur][kk][tx * 8 + 4];
            float a[8] = {a0.x, a0.y, a0.z, a0.w, a1.x, a1.y, a1.z, a1.w};
            float b[8] = {b0.x, b0.y, b0.z, b0.w, b1.x, b1.y, b1.z, b1.w};
#pragma unroll
            for (int i = 0; i < 8; i++)
#pragma unroll
                for (int j = 0; j < 8; j++) acc[i][j] += a[i] * b[j];
        }
        if (kt + 1 < nk) {
            storeA(cur ^ 1); storeB(cur ^ 1);
            __syncthreads();
        }
    }
}

#define GEMM_SMEM                      \
    __shared__ float As[2][8][SP2];    \
    __shared__ float Bs[2][8][SP2];

// ================= K1: qkv = x @ w_qkv^T  (M=32768, N=1536, K=512) =================
__global__ __launch_bounds__(256) void k_qkv(const float* __restrict__ x,
                                             const float* __restrict__ w) {
    GEMM_SMEM
    int m0 = blockIdx.y * 128, n0 = blockIdx.x * 128;
    float acc[8][8] = {};
    gemm128x128<true, true>(x + m0 * 512, 512, w + n0 * 512, 512, 512, acc, As, Bs);
    int tx = threadIdx.x & 15, ty = threadIdx.x >> 4;
#pragma unroll
    for (int i = 0; i < 8; i++) {
        float* dst = &g_qkv[(m0 + ty * 8 + i) * 1536 + n0 + tx * 8];
        *(float4*)dst       = make_float4(acc[i][0], acc[i][1], acc[i][2], acc[i][3]);
        *(float4*)(dst + 4) = make_float4(acc[i][4], acc[i][5], acc[i][6], acc[i][7]);
    }
}

// ================= K2: q token-axis L2 norm inverses =================
__global__ __launch_bounds__(256) void k_qnorm() {
    int bh = blockIdx.x;
    int b = bh >> 3, h = bh & 7;
    int tid = threadIdx.x;
    int d = tid & 63, sl = tid >> 6;
    const float* q = g_qkv + b * (N_ * 1536) + h * 64 + d;
    float s = 0.f;
    for (int n = sl; n < N_; n += 4) {
        float v = q[n * 1536];
        s += v * v;
    }
    __shared__ float red[256];
    red[tid] = s;
    __syncthreads();
    if (sl == 0) {
        float tot = red[d] + red[d + 64] + red[d + 128] + red[d + 192];
        g_qinv[bh * 64 + d] = 1.f / fmaxf(sqrtf(tot), 1e-12f);
    }
}

// ================= K3: kp/vp[p,d] = sum_n w_e[p,n]*K(V)[n,d] + b_e[p] =================
#define SPK 68
__device__ __forceinline__ void fma44(float (&acc)[4][4], const float* Ar,
                                      const float* Br, int ty, int tx) {
    float4 a4 = *(const float4*)(Ar + ty * 4);
    float4 b4 = *(const float4*)(Br + tx * 4);
    float a[4] = {a4.x, a4.y, a4.z, a4.w};
    float b[4] = {b4.x, b4.y, b4.z, b4.w};
#pragma unroll
    for (int i = 0; i < 4; i++)
#pragma unroll
        for (int j = 0; j < 4; j++) acc[i][j] += a[i] * b[j];
}

__global__ __launch_bounds__(256) void k_proj(const float* __restrict__ w_e,
                                              const float* __restrict__ b_e) {
    __shared__ float As[16][SPK];  // [kk][p]
    __shared__ float Bs[16][SPK];  // [kk][d]
    int bh = blockIdx.x, kv = blockIdx.y;
    int b = bh >> 3, h = bh & 7;
    const float* src = g_qkv + b * (N_ * 1536) + 512 * (1 + kv) + h * 64;
    int tid = threadIdx.x;
    int tx = tid & 15, ty = tid >> 4;
    int lkA = tid & 15, lpA = tid >> 4;
    int ldB = tid & 63, lkB = tid >> 6;
    float acc[4][4] = {};
    for (int n0 = 0; n0 < N_; n0 += 16) {
#pragma unroll
        for (int u = 0; u < 4; u++) {
            int p = lpA + 16 * u;
            As[lkA][p] = w_e[p * N_ + n0 + lkA];
            int kk = lkB + 4 * u;
            Bs[kk][ldB] = src[(n0 + kk) * 1536 + ldB];
        }
        __syncthreads();
#pragma unroll
        for (int kk = 0; kk < 16; kk++) fma44(acc, As[kk], Bs[kk], ty, tx);
        __syncthreads();
    }
    float* dst = (kv ? g_vp : g_kp) + bh * (P_ * D_);
#pragma unroll
    for (int i = 0; i < 4; i++) {
        int p = ty * 4 + i;
        float be = b_e[p];
        float4 v = make_float4(acc[i][0] + be, acc[i][1] + be, acc[i][2] + be,
                               acc[i][3] + be);
        *(float4*)&dst[p * 64 + tx * 4] = v;
    }
}

// ================= K4: Gram[b] = X^T X  (512x512, K=4096) =================
__global__ __launch_bounds__(256) void k_gram(const float* __restrict__ x) {
    GEMM_SMEM
    int b = blockIdx.z;
    int c10 = blockIdx.y * 128, c20 = blockIdx.x * 128;
    const float* xb = x + b * (N_ * C_);
    float acc[8][8] = {};
    gemm128x128<false, false>(xb + c10, 512, xb + c20, 512, N_, acc, As, Bs);
    int tx = threadIdx.x & 15, ty = threadIdx.x >> 4;
#pragma unroll
    for (int i = 0; i < 8; i++) {
        float* dst = &g_gram[(b * 512 + c10 + ty * 8 + i) * 512 + c20 + tx * 8];
        *(float4*)dst       = make_float4(acc[i][0], acc[i][1], acc[i][2], acc[i][3]);
        *(float4*)(dst + 4) = make_float4(acc[i][4], acc[i][5], acc[i][6], acc[i][7]);
    }
}

// ================= K5: row softmax of Gram * temperature (in place) =================
__global__ __launch_bounds__(256) void k_softmax512(const float* __restrict__ temp) {
    int row = blockIdx.x;
    float t = temp[0];
    float* p = g_gram + row * 512;
    int tid = threadIdx.x;
    __shared__ float red[256];
    float v0 = p[tid] * t, v1 = p[tid + 256] * t;
    red[tid] = fmaxf(v0, v1);
    __syncthreads();
    for (int s = 128; s > 0; s >>= 1) {
        if (tid < s) red[tid] = fmaxf(red[tid], red[tid + s]);
        __syncthreads();
    }
    float mx = red[0];
    __syncthreads();
    float e0 = __expf(v0 - mx), e1 = __expf(v1 - mx);
    red[tid] = e0 + e1;
    __syncthreads();
    for (int s = 128; s > 0; s >>= 1) {
        if (tid < s) red[tid] += red[tid + s];
        __syncthreads();
    }
    float inv = 1.f / red[0];
    p[tid] = e0 * inv;
    p[tid + 256] = e1 * inv;
}

// ================= K6: fused spatial attention + permute scramble =================
__global__ __launch_bounds__(128) void k_sa(const float* __restrict__ temp2) {
    __shared__ float kp_s[P_ * D_];
    __shared__ float vp_s[P_ * D_];
    __shared__ float qi_s[D_];
    int bh = blockIdx.y;
    int b = bh >> 3, h = bh & 7;
    int n = blockIdx.x * 128 + threadIdx.x;
    const float4* kp4 = (const float4*)(g_kp + bh * (P_ * D_));
    const float4* vp4 = (const float4*)(g_vp + bh * (P_ * D_));
    for (int i = threadIdx.x; i < (P_ * D_) / 4; i += 128) {
        ((float4*)kp_s)[i] = kp4[i];
        ((float4*)vp_s)[i] = vp4[i];
    }
    if (threadIdx.x < 64) qi_s[threadIdx.x] = g_qinv[bh * 64 + threadIdx.x];
    __syncthreads();
    float t2 = temp2[h];
    const float* qrow = g_qkv + b * (N_ * 1536) + n * 1536 + h * 64;

    float q[64];
#pragma unroll
    for (int d = 0; d < 64; d++) q[d] = qrow[d] * qi_s[d];

    float s[64];
    float mx = -1e30f;
#pragma unroll
    for (int p = 0; p < 64; p++) {
        float acc = 0.f;
#pragma unroll
        for (int d = 0; d < 64; d += 4) {
            float4 k4 = *(const float4*)&kp_s[p * 64 + d];
            acc += q[d] * k4.x + q[d + 1] * k4.y + q[d + 2] * k4.z + q[d + 3] * k4.w;
        }
        s[p] = acc * t2;
        mx = fmaxf(mx, s[p]);
    }
    float sum = 0.f;
#pragma unroll
    for (int p = 0; p < 64; p++) {
        s[p] = __expf(s[p] - mx);
        sum += s[p];
    }
    float inv = 1.f / sum;

    float o[64];
#pragma unroll
    for (int d = 0; d < 64; d++) o[d] = 0.f;
#pragma unroll
    for (int p = 0; p < 64; p++) {
        float sp = s[p] * inv;
#pragma unroll
        for (int d = 0; d < 64; d += 4) {
            float4 v4 = *(const float4*)&vp_s[p * 64 + d];
            o[d] += sp * v4.x;
            o[d + 1] += sp * v4.y;
            o[d + 2] += sp * v4.z;
            o[d + 3] += sp * v4.w;
        }
    }
    // faithful permute(0,3,1,2).reshape: row = d*64 + h*8 + (n>>9), col = n&511
    int rbase = h * 8 + (n >> 9);
    int col = n & 511;
    float* xsa = g_xsa + b * (N_ * C_);
#pragma unroll
    for (int d = 0; d < 64; d++) xsa[(d * 64 + rbase) * 512 + col] = o[d];
}

// ================= K7: M[b] = attn^T @ w_o2^T  (512 x 256, K=512) =================
__global__ __launch_bounds__(256) void k_M(const float* __restrict__ w_o2) {
    GEMM_SMEM
    int b = blockIdx.z;
    int m0 = blockIdx.y * 128;  // c'
    int n0 = blockIdx.x * 128;  // j
    const float* A = g_gram + b * (512 * 512);
    float acc[8][8] = {};
    gemm128x128<false, true>(A + m0, 512, w_o2 + n0 * 512, 512, 512, acc, As, Bs);
    int tx = threadIdx.x & 15, ty = threadIdx.x >> 4;
#pragma unroll
    for (int i = 0; i < 8; i++) {
        float* dst = &g_Mmat[(b * 512 + m0 + ty * 8 + i) * 256 + n0 + tx * 8];
        *(float4*)dst       = make_float4(acc[i][0], acc[i][1], acc[i][2], acc[i][3]);
        *(float4*)(dst + 4) = make_float4(acc[i][4], acc[i][5], acc[i][6], acc[i][7]);
    }
}

// ================= K8: out[:, :256] = xsa_scrambled @ w_o1^T + b_o1 =================
__global__ __launch_bounds__(256) void k_out1(const float* __restrict__ w_o1,
                                              const float* __restrict__ b_o1,
                                              float* __restrict__ out) {
    GEMM_SMEM
    int m0 = blockIdx.y * 128, n0 = blockIdx.x * 128;
    float acc[8][8] = {};
    gemm128x128<true, true>(g_xsa + m0 * 512, 512, w_o1 + n0 * 512, 512, 512, acc, As, Bs);
    int tx = threadIdx.x & 15, ty = threadIdx.x >> 4;
#pragma unroll
    for (int i = 0; i < 8; i++) {
        int j0 = n0 + tx * 8;
        float* dst = &out[(m0 + ty * 8 + i) * 512 + j0];
        *(float4*)dst = make_float4(acc[i][0] + b_o1[j0], acc[i][1] + b_o1[j0 + 1],
                                    acc[i][2] + b_o1[j0 + 2], acc[i][3] + b_o1[j0 + 3]);
        *(float4*)(dst + 4) = make_float4(acc[i][4] + b_o1[j0 + 4], acc[i][5] + b_o1[j0 + 5],
                                          acc[i][6] + b_o1[j0 + 6], acc[i][7] + b_o1[j0 + 7]);
    }
}

// ================= K9: out[:, 256:] = x @ M[b] + b_o2 =================
__global__ __launch_bounds__(256) void k_out2(const float* __restrict__ x,
                                              const float* __restrict__ b_o2,
                                              float* __restrict__ out) {
    GEMM_SMEM
    int m0 = blockIdx.y * 128, n0 = blockIdx.x * 128;
    int b = m0 >> 12;  // 4096 rows per batch; 128-row tiles never straddle
    const float* Bm = g_Mmat + b * (512 * 256);
    float acc[8][8] = {};
    gemm128x128<true, false>(x + m0 * 512, 512, Bm + n0, 256, 512, acc, As, Bs);
    int tx = threadIdx.x & 15, ty = threadIdx.x >> 4;
#pragma unroll
    for (int i = 0; i < 8; i++) {
        int j0 = n0 + tx * 8;
        float* dst = &out[(m0 + ty * 8 + i) * 512 + 256 + j0];
        *(float4*)dst = make_float4(acc[i][0] + b_o2[j0], acc[i][1] + b_o2[j0 + 1],
                                    acc[i][2] + b_o2[j0 + 2], acc[i][3] + b_o2[j0 + 3]);
        *(float4*)(dst + 4) = make_float4(acc[i][4] + b_o2[j0 + 4], acc[i][5] + b_o2[j0 + 5],
                                          acc[i][6] + b_o2[j0 + 6], acc[i][7] + b_o2[j0 + 7]);
    }
}

// ================= launch =================
extern "C" void kernel_launch(void* const* d_in, const int* in_sizes, int n_in,
                              void* d_out, int out_size) {
    const float* x      = (const float*)d_in[0];
    const float* w_qkv  = (const float*)d_in[1];
    const float* w_e    = (const float*)d_in[2];
    const float* b_e    = (const float*)d_in[3];
    const float* temp   = (const float*)d_in[4];
    const float* temp2  = (const float*)d_in[5];
    const float* w_o1   = (const float*)d_in[6];
    const float* b_o1   = (const float*)d_in[7];
    const float* w_o2   = (const float*)d_in[8];
    const float* b_o2   = (const float*)d_in[9];
    float* out = (float*)d_out;

    k_qkv<<<dim3(12, 256), 256>>>(x, w_qkv);          // 51.5 GF
    k_qnorm<<<64, 256>>>();                           // reductions
    k_proj<<<dim3(64, 2), 256>>>(w_e, b_e);           // 4.4 GF
    k_gram<<<dim3(4, 4, 8), 256>>>(x);                // 17.2 GF
    k_softmax512<<<B_ * C_, 256>>>(temp);             // in-place
    k_sa<<<dim3(32, 64), 128>>>(temp2);               // fused SA
    k_M<<<dim3(2, 4, 8), 256>>>(w_o2);                // 1.1 GF (fusion)
    k_out1<<<dim3(2, 256), 256>>>(w_o1, b_o1, out);   // 8.6 GF
    k_out2<<<dim3(2, 256), 256>>>(x, b_o2, out);      // 8.6 GF
}

// round 8
// speedup vs baseline: 1.1189x; 1.0201x over previous
#include <cuda_runtime.h>
#include <cuda_bf16.h>
#include <mma.h>
#include <type_traits>
#include <math.h>
#include <cstdint>

using namespace nvcuda;

// Problem constants
#define B_ 8
#define N_ 4096
#define C_ 512
#define H_ 8
#define P_ 64
#define D_ 64

// ---------------- scratch (device globals; no runtime allocation) ----------------
// NOTE: device globals must ONLY be referenced from device code (GB300 ATS
// makes host-shadow writes silently succeed into host memory otherwise).
__device__ float g_qkv[B_ * N_ * 3 * C_];      // [b, n, 1536] fp32
__device__ float g_qinv[B_ * H_ * D_];
__device__ float g_kp[B_ * H_ * P_ * D_];
__device__ float g_vp[B_ * H_ * P_ * D_];
__device__ float g_gram[B_ * C_ * C_];         // softmaxed in place
__device__ __nv_bfloat16 g_xh[B_ * N_ * C_],  g_xl[B_ * N_ * C_];    // x [row, 512]
__device__ __nv_bfloat16 g_wqh[3 * C_ * C_],  g_wql[3 * C_ * C_];    // w_qkv [n, 512]
__device__ __nv_bfloat16 g_wo1h[(C_/2) * C_], g_wo1l[(C_/2) * C_];   // w_o1 [n, 512]
__device__ __nv_bfloat16 g_xsah[B_ * N_ * C_], g_xsal[B_ * N_ * C_]; // scrambled x_sa
__device__ __nv_bfloat16 g_Mh[B_ * (C_/2) * C_], g_Ml[B_ * (C_/2) * C_]; // M^T [b,j,k]

__device__ __forceinline__ void split_bf16(float x, __nv_bfloat16& h, __nv_bfloat16& l) {
    h = __float2bfloat16(x);
    l = __float2bfloat16(x - __bfloat162float(h));
}

// =====================================================================
// wmma bf16 3-pass GEMM: C[128,128] = A*B (fp32), fragments loaded
// directly from global. 256 threads = 8 warps (2m x 4n), warp tile 64x32.
//   matrix_a row: A[m][k] at A[m*lda+k]   col: A[m][k] at A[k*lda+m]
//   matrix_b row: B[k][n] at B[k*ldb+n]   col: B[k][n] at B[n*ldb+k]
// =====================================================================
template <bool ACol, bool BCol>
__device__ __forceinline__ void gemm_wmma(
    const __nv_bfloat16* __restrict__ Ah, const __nv_bfloat16* __restrict__ Al, int lda,
    const __nv_bfloat16* __restrict__ Bh, const __nv_bfloat16* __restrict__ Bl, int ldb,
    int K, float* __restrict__ Cp, int ldc) {
    using ALay = typename std::conditional<ACol, wmma::col_major, wmma::row_major>::type;
    using BLay = typename std::conditional<BCol, wmma::col_major, wmma::row_major>::type;
    int wid = threadIdx.x >> 5;
    int wm = wid & 1, wn = wid >> 1;

    wmma::fragment<wmma::accumulator, 16, 16, 16, float> acc[4][2];
#pragma unroll
    for (int i = 0; i < 4; i++)
#pragma unroll
        for (int j = 0; j < 2; j++) wmma::fill_fragment(acc[i][j], 0.0f);

    for (int k = 0; k < K; k += 16) {
        wmma::fragment<wmma::matrix_a, 16, 16, 16, __nv_bfloat16, ALay> ah[4], al[4];
        wmma::fragment<wmma::matrix_b, 16, 16, 16, __nv_bfloat16, BLay> bh[2], bl[2];
#pragma unroll
        for (int i = 0; i < 4; i++) {
            int m = wm * 64 + i * 16;
            size_t off = ACol ? ((size_t)k * lda + m) : ((size_t)m * lda + k);
            wmma::load_matrix_sync(ah[i], Ah + off, lda);
            wmma::load_matrix_sync(al[i], Al + off, lda);
        }
#pragma unroll
        for (int j = 0; j < 2; j++) {
            int n = wn * 32 + j * 16;
            size_t off = BCol ? ((size_t)n * ldb + k) : ((size_t)k * ldb + n);
            wmma::load_matrix_sync(bh[j], Bh + off, ldb);
            wmma::load_matrix_sync(bl[j], Bl + off, ldb);
        }
#pragma unroll
        for (int i = 0; i < 4; i++)
#pragma unroll
            for (int j = 0; j < 2; j++) {
                wmma::mma_sync(acc[i][j], ah[i], bh[j], acc[i][j]);
                wmma::mma_sync(acc[i][j], ah[i], bl[j], acc[i][j]);
                wmma::mma_sync(acc[i][j], al[i], bh[j], acc[i][j]);
            }
    }
#pragma unroll
    for (int i = 0; i < 4; i++)
#pragma unroll
        for (int j = 0; j < 2; j++) {
            int m = wm * 64 + i * 16, n = wn * 32 + j * 16;
            wmma::store_matrix_sync(Cp + (size_t)m * ldc + n, acc[i][j], ldc,
                                    wmma::mem_row_major);
        }
}

// ================= K1: qkv = x @ w_qkv^T =================
__global__ __launch_bounds__(256) void k_qkv_w() {
    int m0 = blockIdx.y * 128, n0 = blockIdx.x * 128;
    gemm_wmma<false, true>(g_xh + (size_t)m0 * 512, g_xl + (size_t)m0 * 512, 512,
                           g_wqh + (size_t)n0 * 512, g_wql + (size_t)n0 * 512, 512,
                           512, g_qkv + (size_t)m0 * 1536 + n0, 1536);
}

// ================= K4: Gram[b] = X^T X (A col-major view of x) =================
__global__ __launch_bounds__(256) void k_gram_w() {
    int b = blockIdx.z;
    int c10 = blockIdx.y * 128, c20 = blockIdx.x * 128;
    const __nv_bfloat16* xh = g_xh + (size_t)b * N_ * C_;
    const __nv_bfloat16* xl = g_xl + (size_t)b * N_ * C_;
    gemm_wmma<true, false>(xh + c10, xl + c10, 512, xh + c20, xl + c20, 512,
                           N_, g_gram + ((size_t)(b * 512 + c10)) * 512 + c20, 512);
}

// ================= K8: out[:, :256] = xsa @ w_o1^T =================
__global__ __launch_bounds__(256) void k_out1_w(float* __restrict__ out) {
    int m0 = blockIdx.y * 128, n0 = blockIdx.x * 128;
    gemm_wmma<false, true>(g_xsah + (size_t)m0 * 512, g_xsal + (size_t)m0 * 512, 512,
                           g_wo1h + (size_t)n0 * 512, g_wo1l + (size_t)n0 * 512, 512,
                           512, out + (size_t)m0 * 512 + n0, 512);
}

// ================= K9: out[:, 256:] = x @ M[b] =================
__global__ __launch_bounds__(256) void k_out2_w(float* __restrict__ out) {
    int m0 = blockIdx.y * 128, n0 = blockIdx.x * 128;
    int b = m0 >> 12;
    gemm_wmma<false, true>(g_xh + (size_t)m0 * 512, g_xl + (size_t)m0 * 512, 512,
                           g_Mh + ((size_t)b * 256 + n0) * 512,
                           g_Ml + ((size_t)b * 256 + n0) * 512, 512,
                           512, out + (size_t)m0 * 512 + 256 + n0, 512);
}

// ================= bias epilogue: out[r][c] += b_o1/b_o2 =================
__global__ __launch_bounds__(256) void k_bias(const float* __restrict__ b_o1,
                                              const float* __restrict__ b_o2,
                                              float* __restrict__ out) {
    size_t i = ((size_t)blockIdx.x * 256 + threadIdx.x) * 4;
    int c = (int)(i & 511);
    const float* bias = (c < 256) ? (b_o1 + c) : (b_o2 + c - 256);
    float4 v = *(float4*)(out + i);
    float4 bb = *(const float4*)bias;
    v.x += bb.x; v.y += bb.y; v.z += bb.z; v.w += bb.w;
    *(float4*)(out + i) = v;
}

// ================= conversions (destinations referenced in DEVICE code) =====
__device__ __forceinline__ void split4_to(const float* __restrict__ s,
                                          __nv_bfloat16* __restrict__ h,
                                          __nv_bfloat16* __restrict__ l, size_t i) {
    float4 v = *(const float4*)(s + i);
    __nv_bfloat16 hh[4], ll[4];
    split_bf16(v.x, hh[0], ll[0]); split_bf16(v.y, hh[1], ll[1]);
    split_bf16(v.z, hh[2], ll[2]); split_bf16(v.w, hh[3], ll[3]);
    *(uint2*)(h + i) = *(uint2*)hh;
    *(uint2*)(l + i) = *(uint2*)ll;
}

__global__ void c_split_x(const float* __restrict__ s) {
    size_t i = ((size_t)blockIdx.x * 256 + threadIdx.x) * 4;
    split4_to(s, g_xh, g_xl, i);          // device-side symbol reference
}
__global__ void c_split_wq(const float* __restrict__ s) {
    size_t i = ((size_t)blockIdx.x * 256 + threadIdx.x) * 4;
    split4_to(s, g_wqh, g_wql, i);
}
__global__ void c_split_wo1(const float* __restrict__ s) {
    size_t i = ((size_t)blockIdx.x * 256 + threadIdx.x) * 4;
    split4_to(s, g_wo1h, g_wo1l, i);
}

// ================= K2: q token-axis L2 norm inverses =================
__global__ __launch_bounds__(256) void k_qnorm() {
    int bh = blockIdx.x;
    int b = bh >> 3, h = bh & 7;
    int tid = threadIdx.x;
    int d = tid & 63, sl = tid >> 6;
    const float* q = g_qkv + (size_t)b * (N_ * 1536) + h * 64 + d;
    float s = 0.f;
    for (int n = sl; n < N_; n += 4) {
        float v = q[(size_t)n * 1536];
        s += v * v;
    }
    __shared__ float red[256];
    red[tid] = s;
    __syncthreads();
    if (sl == 0) {
        float tot = red[d] + red[d + 64] + red[d + 128] + red[d + 192];
        g_qinv[bh * 64 + d] = 1.f / fmaxf(sqrtf(tot), 1e-12f);
    }
}

// ================= K3: kp/vp = w_e @ K(V) + b_e (FFMA, small) =================
#define SPK 68
__device__ __forceinline__ void fma44(float (&acc)[4][4], const float* Ar,
                                      const float* Br, int ty, int tx) {
    float4 a4 = *(const float4*)(Ar + ty * 4);
    float4 b4 = *(const float4*)(Br + tx * 4);
    float a[4] = {a4.x, a4.y, a4.z, a4.w};
    float b[4] = {b4.x, b4.y, b4.z, b4.w};
#pragma unroll
    for (int i = 0; i < 4; i++)
#pragma unroll
        for (int j = 0; j < 4; j++) acc[i][j] += a[i] * b[j];
}

__global__ __launch_bounds__(256) void k_proj(const float* __restrict__ w_e,
                                              const float* __restrict__ b_e) {
    __shared__ float As[16][SPK];
    __shared__ float Bs[16][SPK];
    int bh = blockIdx.x, kv = blockIdx.y;
    int b = bh >> 3, h = bh & 7;
    const float* src = g_qkv + (size_t)b * (N_ * 1536) + 512 * (1 + kv) + h * 64;
    int tid = threadIdx.x;
    int tx = tid & 15, ty = tid >> 4;
    int lkA = tid & 15, lpA = tid >> 4;
    int ldB = tid & 63, lkB = tid >> 6;
    float acc[4][4] = {};
    for (int n0 = 0; n0 < N_; n0 += 16) {
#pragma unroll
        for (int u = 0; u < 4; u++) {
            int p = lpA + 16 * u;
            As[lkA][p] = w_e[(size_t)p * N_ + n0 + lkA];
            int kk = lkB + 4 * u;
            Bs[kk][ldB] = src[(size_t)(n0 + kk) * 1536 + ldB];
        }
        __syncthreads();
#pragma unroll
        for (int kk = 0; kk < 16; kk++) fma44(acc, As[kk], Bs[kk], ty, tx);
        __syncthreads();
    }
    float* dst = (kv ? g_vp : g_kp) + bh * (P_ * D_);
#pragma unroll
    for (int i = 0; i < 4; i++) {
        int p = ty * 4 + i;
        float be = b_e[p];
        *(float4*)&dst[p * 64 + tx * 4] = make_float4(
            acc[i][0] + be, acc[i][1] + be, acc[i][2] + be, acc[i][3] + be);
    }
}

// ================= K5: row softmax of Gram * temperature =================
__global__ __launch_bounds__(256) void k_softmax512(const float* __restrict__ temp) {
    int row = blockIdx.x;
    float t = temp[0];
    float* p = g_gram + (size_t)row * 512;
    int tid = threadIdx.x;
    __shared__ float red[256];
    float v0 = p[tid] * t, v1 = p[tid + 256] * t;
    red[tid] = fmaxf(v0, v1);
    __syncthreads();
    for (int s = 128; s > 0; s >>= 1) {
        if (tid < s) red[tid] = fmaxf(red[tid], red[tid + s]);
        __syncthreads();
    }
    float mx = red[0];
    __syncthreads();
    float e0 = __expf(v0 - mx), e1 = __expf(v1 - mx);
    red[tid] = e0 + e1;
    __syncthreads();
    for (int s = 128; s > 0; s >>= 1) {
        if (tid < s) red[tid] += red[tid + s];
        __syncthreads();
    }
    float inv = 1.f / red[0];
    p[tid] = e0 * inv;
    p[tid + 256] = e1 * inv;
}

// ================= K6: fused spatial attention (writes bf16 hi/lo) =================
__global__ __launch_bounds__(128) void k_sa(const float* __restrict__ temp2) {
    __shared__ float kp_s[P_ * D_];
    __shared__ float vp_s[P_ * D_];
    __shared__ float qi_s[D_];
    int bh = blockIdx.y;
    int b = bh >> 3, h = bh & 7;
    int n = blockIdx.x * 128 + threadIdx.x;
    const float4* kp4 = (const float4*)(g_kp + bh * (P_ * D_));
    const float4* vp4 = (const float4*)(g_vp + bh * (P_ * D_));
    for (int i = threadIdx.x; i < (P_ * D_) / 4; i += 128) {
        ((float4*)kp_s)[i] = kp4[i];
        ((float4*)vp_s)[i] = vp4[i];
    }
    if (threadIdx.x < 64) qi_s[threadIdx.x] = g_qinv[bh * 64 + threadIdx.x];
    __syncthreads();
    float t2 = temp2[h];
    const float* qrow = g_qkv + (size_t)b * (N_ * 1536) + (size_t)n * 1536 + h * 64;

    float q[64];
#pragma unroll
    for (int d = 0; d < 64; d++) q[d] = qrow[d] * qi_s[d];

    float s[64];
    float mx = -1e30f;
#pragma unroll
    for (int p = 0; p < 64; p++) {
        float acc = 0.f;
#pragma unroll
        for (int d = 0; d < 64; d += 4) {
            float4 k4 = *(const float4*)&kp_s[p * 64 + d];
            acc += q[d] * k4.x + q[d + 1] * k4.y + q[d + 2] * k4.z + q[d + 3] * k4.w;
        }
        s[p] = acc * t2;
        mx = fmaxf(mx, s[p]);
    }
    float sum = 0.f;
#pragma unroll
    for (int p = 0; p < 64; p++) {
        s[p] = __expf(s[p] - mx);
        sum += s[p];
    }
    float inv = 1.f / sum;

    float o[64];
#pragma unroll
    for (int d = 0; d < 64; d++) o[d] = 0.f;
#pragma unroll
    for (int p = 0; p < 64; p++) {
        float sp = s[p] * inv;
#pragma unroll
        for (int d = 0; d < 64; d += 4) {
            float4 v4 = *(const float4*)&vp_s[p * 64 + d];
            o[d] += sp * v4.x;
            o[d + 1] += sp * v4.y;
            o[d + 2] += sp * v4.z;
            o[d + 3] += sp * v4.w;
        }
    }
    int rbase = h * 8 + (n >> 9);
    int col = n & 511;
    size_t boff = (size_t)b * (N_ * C_);
#pragma unroll
    for (int d = 0; d < 64; d++) {
        __nv_bfloat16 hh, ll;
        split_bf16(o[d], hh, ll);
        size_t idx = boff + (size_t)(d * 64 + rbase) * 512 + col;
        g_xsah[idx] = hh;
        g_xsal[idx] = ll;
    }
}

// ================= K7: M^T[b,j,k] = (attn^T @ w_o2^T)^T, bf16 hi/lo out =================
#define SP2 132
template <bool AT, bool BT>
__device__ __forceinline__ void gemm128x128(
    const float* __restrict__ A, int lda, const float* __restrict__ B, int ldb,
    int K, float (&acc)[8][8], float (*As)[8][SP2], float (*Bs)[8][SP2]) {
    int tid = threadIdx.x;
    int tx = tid & 15, ty = tid >> 4;
    int rowT = tid >> 1, kqT = (tid & 1) * 4;
    int krD = tid >> 5, mqD = (tid & 31) * 4;
    float4 ra, rb;
    auto loadA = [&](int k0) {
        if (AT) ra = *(const float4*)&A[(size_t)rowT * lda + k0 + kqT];
        else    ra = *(const float4*)&A[(size_t)(k0 + krD) * lda + mqD];
    };
    auto loadB = [&](int k0) {
        if (BT) rb = *(const float4*)&B[(size_t)rowT * ldb + k0 + kqT];
        else    rb = *(const float4*)&B[(size_t)(k0 + krD) * ldb + mqD];
    };
    auto storeA = [&](int buf) {
        if (AT) {
            As[buf][kqT + 0][rowT] = ra.x; As[buf][kqT + 1][rowT] = ra.y;
            As[buf][kqT + 2][rowT] = ra.z; As[buf][kqT + 3][rowT] = ra.w;
        } else *(float4*)&As[buf][krD][mqD] = ra;
    };
    auto storeB = [&](int buf) {
        if (BT) {
            Bs[buf][kqT + 0][rowT] = rb.x; Bs[buf][kqT + 1][rowT] = rb.y;
            Bs[buf][kqT + 2][rowT] = rb.z; Bs[buf][kqT + 3][rowT] = rb.w;
        } else *(float4*)&Bs[buf][krD][mqD] = rb;
    };
    loadA(0); loadB(0); storeA(0); storeB(0);
    __syncthreads();
    int nk = K >> 3;
    for (int kt = 0; kt < nk; kt++) {
        int cur = kt & 1;
        if (kt + 1 < nk) { loadA((kt + 1) << 3); loadB((kt + 1) << 3); }
#pragma unroll
        for (int kk = 0; kk < 8; kk++) {
            float4 a0 = *(const float4*)&As[cur][kk][ty * 8];
            float4 a1 = *(const float4*)&As[cur][kk][ty * 8 + 4];
            float4 b0 = *(const float4*)&Bs[cur][kk][tx * 8];
            float4 b1 = *(const float4*)&Bs[cur][kk][tx * 8 + 4];
            float a[8] = {a0.x, a0.y, a0.z, a0.w, a1.x, a1.y, a1.z, a1.w};
            float b[8] = {b0.x, b0.y, b0.z, b0.w, b1.x, b1.y, b1.z, b1.w};
#pragma unroll
            for (int i = 0; i < 8; i++)
#pragma unroll
                for (int j = 0; j < 8; j++) acc[i][j] += a[i] * b[j];
        }
        if (kt + 1 < nk) { storeA(cur ^ 1); storeB(cur ^ 1); __syncthreads(); }
    }
}

__global__ __launch_bounds__(256) void k_M(const float* __restrict__ w_o2) {
    __shared__ float As[2][8][SP2];
    __shared__ float Bs[2][8][SP2];
    int b = blockIdx.z;
    int m0 = blockIdx.y * 128;  // c'
    int n0 = blockIdx.x * 128;  // j (only 2 tiles: 256 cols)
    const float* A = g_gram + (size_t)b * (512 * 512);
    float acc[8][8] = {};
    gemm128x128<false, true>(A + m0, 512, w_o2 + (size_t)n0 * 512, 512, 512, acc, As, Bs);
    int tx = threadIdx.x & 15, ty = threadIdx.x >> 4;
#pragma unroll
    for (int i = 0; i < 8; i++) {
        int k = m0 + ty * 8 + i;
#pragma unroll
        for (int jj = 0; jj < 8; jj++) {
            int j = n0 + tx * 8 + jj;
            __nv_bfloat16 hh, ll;
            split_bf16(acc[i][jj], hh, ll);
            size_t idx = ((size_t)b * 256 + j) * 512 + k;
            g_Mh[idx] = hh;
            g_Ml[idx] = ll;
        }
    }
}

// ================= launch =================
extern "C" void kernel_launch(void* const* d_in, const int* in_sizes, int n_in,
                              void* d_out, int out_size) {
    const float* x      = (const float*)d_in[0];
    const float* w_qkv  = (const float*)d_in[1];
    const float* w_e    = (const float*)d_in[2];
    const float* b_e    = (const float*)d_in[3];
    const float* temp   = (const float*)d_in[4];
    const float* temp2  = (const float*)d_in[5];
    const float* w_o1   = (const float*)d_in[6];
    const float* b_o1   = (const float*)d_in[7];
    const float* w_o2   = (const float*)d_in[8];
    const float* b_o2   = (const float*)d_in[9];
    float* out = (float*)d_out;

    // bf16 hi/lo conversions (globals referenced inside kernels only)
    c_split_x<<<(B_ * N_ * C_) / 1024, 256>>>(x);
    c_split_wq<<<(3 * C_ * C_) / 1024, 256>>>(w_qkv);
    c_split_wo1<<<((C_ / 2) * C_) / 1024, 256>>>(w_o1);

    k_qkv_w<<<dim3(12, 256), 256>>>();            // 51.5 GF (x3 passes)
    k_qnorm<<<64, 256>>>();
    k_proj<<<dim3(64, 2), 256>>>(w_e, b_e);
    k_gram_w<<<dim3(4, 4, 8), 256>>>();           // 17.2 GF
    k_softmax512<<<B_ * C_, 256>>>(temp);
    k_sa<<<dim3(32, 64), 128>>>(temp2);
    k_M<<<dim3(2, 4, 8), 256>>>(w_o2);            // j has 2 tiles (256 cols)
    k_out1_w<<<dim3(2, 256), 256>>>(out);         // 8.6 GF
    k_out2_w<<<dim3(2, 256), 256>>>(out);         // 8.6 GF
    k_bias<<<(B_ * N_ * C_) / 1024, 256>>>(b_o1, b_o2, out);
}

// round 9
// speedup vs baseline: 1.5197x; 1.3582x over previous
#include <cuda_runtime.h>
#include <cuda_bf16.h>
#include <mma.h>
#include <type_traits>
#include <math.h>
#include <cstdint>

using namespace nvcuda;

// Problem constants
#define B_ 8
#define N_ 4096
#define C_ 512
#define H_ 8
#define P_ 64
#define D_ 64

// ---------------- scratch (device globals; no runtime allocation) ----------------
// NOTE: device globals must ONLY be referenced from device code (GB300 ATS
// makes host-shadow writes silently succeed into host memory otherwise).
__device__ float g_qkv[B_ * N_ * 3 * C_];      // [b, n, 1536] fp32
__device__ float g_qinv[B_ * H_ * D_];
__device__ float g_kp[B_ * H_ * P_ * D_];
__device__ float g_vp[B_ * H_ * P_ * D_];
__device__ float g_gram[B_ * C_ * C_];         // softmaxed in place
__device__ __nv_bfloat16 g_xh[B_ * N_ * C_],  g_xl[B_ * N_ * C_];    // x [row, 512]
__device__ __nv_bfloat16 g_wqh[3 * C_ * C_],  g_wql[3 * C_ * C_];    // w_qkv [n, 512]
__device__ __nv_bfloat16 g_wo1h[(C_/2) * C_], g_wo1l[(C_/2) * C_];   // w_o1 [n, 512]
__device__ __nv_bfloat16 g_xsah[B_ * N_ * C_], g_xsal[B_ * N_ * C_]; // scrambled x_sa
__device__ __nv_bfloat16 g_Mh[B_ * (C_/2) * C_], g_Ml[B_ * (C_/2) * C_]; // M^T [b,j,k]

__device__ __forceinline__ void split_bf16(float x, __nv_bfloat16& h, __nv_bfloat16& l) {
    h = __float2bfloat16(x);
    l = __float2bfloat16(x - __bfloat162float(h));
}

// =====================================================================
// wmma bf16 3-pass GEMM with SMEM staging: C[128,128] = A*B (fp32).
// 256 threads = 8 warps (2m x 4n), warp tile 64x32, K chunks of 32.
// Operand tiles staged to smem once per chunk (uint4 ld/st), fragments
// loaded from smem. Row-major tile: 128 x RSTR; col(k-rows): 32 x KSTR.
//   matrix_a row: A[m][k] at A[m*lda+k]   col: A[m][k] at A[k*lda+m]
//   matrix_b col: B[k][n] at B[n*ldb+k]   row: B[k][n] at B[k*ldb+n]
// =====================================================================
#define RSTR 40
#define KSTR 136

template <bool ACol, bool BCol>
__device__ __forceinline__ void gemm_wmma_s(
    const __nv_bfloat16* __restrict__ Ah, const __nv_bfloat16* __restrict__ Al, int lda,
    const __nv_bfloat16* __restrict__ Bh, const __nv_bfloat16* __restrict__ Bl, int ldb,
    int K, float* __restrict__ Cp, int ldc) {
    using ALay = typename std::conditional<ACol, wmma::col_major, wmma::row_major>::type;
    using BLay = typename std::conditional<BCol, wmma::col_major, wmma::row_major>::type;
    // B memory-[n][k] (BCol=true) stages like a row-major 128xRSTR tile;
    // B memory-[k][n] (BCol=false) stages like a 32xKSTR tile.
    __shared__ __nv_bfloat16 sAh[ACol ? 32 * KSTR : 128 * RSTR];
    __shared__ __nv_bfloat16 sAl[ACol ? 32 * KSTR : 128 * RSTR];
    __shared__ __nv_bfloat16 sBh[BCol ? 128 * RSTR : 32 * KSTR];
    __shared__ __nv_bfloat16 sBl[BCol ? 128 * RSTR : 32 * KSTR];

    int tid = threadIdx.x;
    int wid = tid >> 5;
    int wm = wid & 1, wn = wid >> 1;

    uint4 rAh[2], rAl[2], rBh[2], rBl[2];

    auto LD = [&](int k0) {
#pragma unroll
        for (int u = 0; u < 2; u++) {
            int idx = u * 256 + tid;
            if (ACol) {
                int kr = idx >> 4, q = idx & 15;
                size_t o = (size_t)(k0 + kr) * lda + q * 8;
                rAh[u] = *(const uint4*)(Ah + o);
                rAl[u] = *(const uint4*)(Al + o);
            } else {
                int row = idx >> 2, q = idx & 3;
                size_t o = (size_t)row * lda + k0 + q * 8;
                rAh[u] = *(const uint4*)(Ah + o);
                rAl[u] = *(const uint4*)(Al + o);
            }
            if (BCol) {
                int row = idx >> 2, q = idx & 3;
                size_t o = (size_t)row * ldb + k0 + q * 8;
                rBh[u] = *(const uint4*)(Bh + o);
                rBl[u] = *(const uint4*)(Bl + o);
            } else {
                int kr = idx >> 4, q = idx & 15;
                size_t o = (size_t)(k0 + kr) * ldb + q * 8;
                rBh[u] = *(const uint4*)(Bh + o);
                rBl[u] = *(const uint4*)(Bl + o);
            }
        }
    };
    auto ST = [&]() {
#pragma unroll
        for (int u = 0; u < 2; u++) {
            int idx = u * 256 + tid;
            if (ACol) {
                int kr = idx >> 4, q = idx & 15;
                *(uint4*)(sAh + kr * KSTR + q * 8) = rAh[u];
                *(uint4*)(sAl + kr * KSTR + q * 8) = rAl[u];
            } else {
                int row = idx >> 2, q = idx & 3;
                *(uint4*)(sAh + row * RSTR + q * 8) = rAh[u];
                *(uint4*)(sAl + row * RSTR + q * 8) = rAl[u];
            }
            if (BCol) {
                int row = idx >> 2, q = idx & 3;
                *(uint4*)(sBh + row * RSTR + q * 8) = rBh[u];
                *(uint4*)(sBl + row * RSTR + q * 8) = rBl[u];
            } else {
                int kr = idx >> 4, q = idx & 15;
                *(uint4*)(sBh + kr * KSTR + q * 8) = rBh[u];
                *(uint4*)(sBl + kr * KSTR + q * 8) = rBl[u];
            }
        }
    };

    wmma::fragment<wmma::accumulator, 16, 16, 16, float> acc[4][2];
#pragma unroll
    for (int i = 0; i < 4; i++)
#pragma unroll
        for (int j = 0; j < 2; j++) wmma::fill_fragment(acc[i][j], 0.0f);

    LD(0); ST();
    __syncthreads();

    int nk = K >> 5;
    for (int kt = 0; kt < nk; kt++) {
        if (kt + 1 < nk) LD((kt + 1) << 5);   // overlap global loads with MMAs
#pragma unroll
        for (int kk = 0; kk < 32; kk += 16) {
            wmma::fragment<wmma::matrix_a, 16, 16, 16, __nv_bfloat16, ALay> ah[4], al[4];
            wmma::fragment<wmma::matrix_b, 16, 16, 16, __nv_bfloat16, BLay> bh[2], bl[2];
#pragma unroll
            for (int i = 0; i < 4; i++) {
                int m = wm * 64 + i * 16;
                if (ACol) {
                    wmma::load_matrix_sync(ah[i], sAh + kk * KSTR + m, KSTR);
                    wmma::load_matrix_sync(al[i], sAl + kk * KSTR + m, KSTR);
                } else {
                    wmma::load_matrix_sync(ah[i], sAh + m * RSTR + kk, RSTR);
                    wmma::load_matrix_sync(al[i], sAl + m * RSTR + kk, RSTR);
                }
            }
#pragma unroll
            for (int j = 0; j < 2; j++) {
                int n = wn * 32 + j * 16;
                if (BCol) {
                    wmma::load_matrix_sync(bh[j], sBh + n * RSTR + kk, RSTR);
                    wmma::load_matrix_sync(bl[j], sBl + n * RSTR + kk, RSTR);
                } else {
                    wmma::load_matrix_sync(bh[j], sBh + kk * KSTR + n, KSTR);
                    wmma::load_matrix_sync(bl[j], sBl + kk * KSTR + n, KSTR);
                }
            }
#pragma unroll
            for (int i = 0; i < 4; i++)
#pragma unroll
                for (int j = 0; j < 2; j++) {
                    wmma::mma_sync(acc[i][j], ah[i], bh[j], acc[i][j]);
                    wmma::mma_sync(acc[i][j], ah[i], bl[j], acc[i][j]);
                    wmma::mma_sync(acc[i][j], al[i], bh[j], acc[i][j]);
                }
        }
        if (kt + 1 < nk) {
            __syncthreads();   // all warps done with current tiles
            ST();
            __syncthreads();   // next tiles visible
        }
    }
#pragma unroll
    for (int i = 0; i < 4; i++)
#pragma unroll
        for (int j = 0; j < 2; j++) {
            int m = wm * 64 + i * 16, n = wn * 32 + j * 16;
            wmma::store_matrix_sync(Cp + (size_t)m * ldc + n, acc[i][j], ldc,
                                    wmma::mem_row_major);
        }
}

// ================= K1: qkv = x @ w_qkv^T =================
__global__ __launch_bounds__(256) void k_qkv_w() {
    int m0 = blockIdx.y * 128, n0 = blockIdx.x * 128;
    gemm_wmma_s<false, true>(g_xh + (size_t)m0 * 512, g_xl + (size_t)m0 * 512, 512,
                             g_wqh + (size_t)n0 * 512, g_wql + (size_t)n0 * 512, 512,
                             512, g_qkv + (size_t)m0 * 1536 + n0, 1536);
}

// ================= K4: Gram[b] = X^T X (A col-major view of x) =================
__global__ __launch_bounds__(256) void k_gram_w() {
    int b = blockIdx.z;
    int c10 = blockIdx.y * 128, c20 = blockIdx.x * 128;
    const __nv_bfloat16* xh = g_xh + (size_t)b * N_ * C_;
    const __nv_bfloat16* xl = g_xl + (size_t)b * N_ * C_;
    gemm_wmma_s<true, false>(xh + c10, xl + c10, 512, xh + c20, xl + c20, 512,
                             N_, g_gram + ((size_t)(b * 512 + c10)) * 512 + c20, 512);
}

// ================= K8: out[:, :256] = xsa @ w_o1^T =================
__global__ __launch_bounds__(256) void k_out1_w(float* __restrict__ out) {
    int m0 = blockIdx.y * 128, n0 = blockIdx.x * 128;
    gemm_wmma_s<false, true>(g_xsah + (size_t)m0 * 512, g_xsal + (size_t)m0 * 512, 512,
                             g_wo1h + (size_t)n0 * 512, g_wo1l + (size_t)n0 * 512, 512,
                             512, out + (size_t)m0 * 512 + n0, 512);
}

// ================= K9: out[:, 256:] = x @ M[b] =================
__global__ __launch_bounds__(256) void k_out2_w(float* __restrict__ out) {
    int m0 = blockIdx.y * 128, n0 = blockIdx.x * 128;
    int b = m0 >> 12;
    gemm_wmma_s<false, true>(g_xh + (size_t)m0 * 512, g_xl + (size_t)m0 * 512, 512,
                             g_Mh + ((size_t)b * 256 + n0) * 512,
                             g_Ml + ((size_t)b * 256 + n0) * 512, 512,
                             512, out + (size_t)m0 * 512 + 256 + n0, 512);
}

// ================= bias epilogue: out[r][c] += b_o1/b_o2 =================
__global__ __launch_bounds__(256) void k_bias(const float* __restrict__ b_o1,
                                              const float* __restrict__ b_o2,
                                              float* __restrict__ out) {
    size_t i = ((size_t)blockIdx.x * 256 + threadIdx.x) * 4;
    int c = (int)(i & 511);
    const float* bias = (c < 256) ? (b_o1 + c) : (b_o2 + c - 256);
    float4 v = *(float4*)(out + i);
    float4 bb = *(const float4*)bias;
    v.x += bb.x; v.y += bb.y; v.z += bb.z; v.w += bb.w;
    *(float4*)(out + i) = v;
}

// ================= conversions (destinations referenced in DEVICE code) =====
__device__ __forceinline__ void split4_to(const float* __restrict__ s,
                                          __nv_bfloat16* __restrict__ h,
                                          __nv_bfloat16* __restrict__ l, size_t i) {
    float4 v = *(const float4*)(s + i);
    __nv_bfloat16 hh[4], ll[4];
    split_bf16(v.x, hh[0], ll[0]); split_bf16(v.y, hh[1], ll[1]);
    split_bf16(v.z, hh[2], ll[2]); split_bf16(v.w, hh[3], ll[3]);
    *(uint2*)(h + i) = *(uint2*)hh;
    *(uint2*)(l + i) = *(uint2*)ll;
}

__global__ void c_split_x(const float* __restrict__ s) {
    size_t i = ((size_t)blockIdx.x * 256 + threadIdx.x) * 4;
    split4_to(s, g_xh, g_xl, i);          // device-side symbol reference
}
__global__ void c_split_wq(const float* __restrict__ s) {
    size_t i = ((size_t)blockIdx.x * 256 + threadIdx.x) * 4;
    split4_to(s, g_wqh, g_wql, i);
}
__global__ void c_split_wo1(const float* __restrict__ s) {
    size_t i = ((size_t)blockIdx.x * 256 + threadIdx.x) * 4;
    split4_to(s, g_wo1h, g_wo1l, i);
}

// ================= K2: q token-axis L2 norm inverses =================
__global__ __launch_bounds__(256) void k_qnorm() {
    int bh = blockIdx.x;
    int b = bh >> 3, h = bh & 7;
    int tid = threadIdx.x;
    int d = tid & 63, sl = tid >> 6;
    const float* q = g_qkv + (size_t)b * (N_ * 1536) + h * 64 + d;
    float s = 0.f;
    for (int n = sl; n < N_; n += 4) {
        float v = q[(size_t)n * 1536];
        s += v * v;
    }
    __shared__ float red[256];
    red[tid] = s;
    __syncthreads();
    if (sl == 0) {
        float tot = red[d] + red[d + 64] + red[d + 128] + red[d + 192];
        g_qinv[bh * 64 + d] = 1.f / fmaxf(sqrtf(tot), 1e-12f);
    }
}

// ================= K3: kp/vp = w_e @ K(V) + b_e (FFMA, small) =================
#define SPK 68
__device__ __forceinline__ void fma44(float (&acc)[4][4], const float* Ar,
                                      const float* Br, int ty, int tx) {
    float4 a4 = *(const float4*)(Ar + ty * 4);
    float4 b4 = *(const float4*)(Br + tx * 4);
    float a[4] = {a4.x, a4.y, a4.z, a4.w};
    float b[4] = {b4.x, b4.y, b4.z, b4.w};
#pragma unroll
    for (int i = 0; i < 4; i++)
#pragma unroll
        for (int j = 0; j < 4; j++) acc[i][j] += a[i] * b[j];
}

__global__ __launch_bounds__(256) void k_proj(const float* __restrict__ w_e,
                                              const float* __restrict__ b_e) {
    __shared__ float As[16][SPK];
    __shared__ float Bs[16][SPK];
    int bh = blockIdx.x, kv = blockIdx.y;
    int b = bh >> 3, h = bh & 7;
    const float* src = g_qkv + (size_t)b * (N_ * 1536) + 512 * (1 + kv) + h * 64;
    int tid = threadIdx.x;
    int tx = tid & 15, ty = tid >> 4;
    int lkA = tid & 15, lpA = tid >> 4;
    int ldB = tid & 63, lkB = tid >> 6;
    float acc[4][4] = {};
    for (int n0 = 0; n0 < N_; n0 += 16) {
#pragma unroll
        for (int u = 0; u < 4; u++) {
            int p = lpA + 16 * u;
            As[lkA][p] = w_e[(size_t)p * N_ + n0 + lkA];
            int kk = lkB + 4 * u;
            Bs[kk][ldB] = src[(size_t)(n0 + kk) * 1536 + ldB];
        }
        __syncthreads();
#pragma unroll
        for (int kk = 0; kk < 16; kk++) fma44(acc, As[kk], Bs[kk], ty, tx);
        __syncthreads();
    }
    float* dst = (kv ? g_vp : g_kp) + bh * (P_ * D_);
#pragma unroll
    for (int i = 0; i < 4; i++) {
        int p = ty * 4 + i;
        float be = b_e[p];
        *(float4*)&dst[p * 64 + tx * 4] = make_float4(
            acc[i][0] + be, acc[i][1] + be, acc[i][2] + be, acc[i][3] + be);
    }
}

// ================= K5: row softmax of Gram * temperature =================
__global__ __launch_bounds__(256) void k_softmax512(const float* __restrict__ temp) {
    int row = blockIdx.x;
    float t = temp[0];
    float* p = g_gram + (size_t)row * 512;
    int tid = threadIdx.x;
    __shared__ float red[256];
    float v0 = p[tid] * t, v1 = p[tid + 256] * t;
    red[tid] = fmaxf(v0, v1);
    __syncthreads();
    for (int s = 128; s > 0; s >>= 1) {
        if (tid < s) red[tid] = fmaxf(red[tid], red[tid + s]);
        __syncthreads();
    }
    float mx = red[0];
    __syncthreads();
    float e0 = __expf(v0 - mx), e1 = __expf(v1 - mx);
    red[tid] = e0 + e1;
    __syncthreads();
    for (int s = 128; s > 0; s >>= 1) {
        if (tid < s) red[tid] += red[tid + s];
        __syncthreads();
    }
    float inv = 1.f / red[0];
    p[tid] = e0 * inv;
    p[tid + 256] = e1 * inv;
}

// ================= K6: fused spatial attention (writes bf16 hi/lo) =================
__global__ __launch_bounds__(128) void k_sa(const float* __restrict__ temp2) {
    __shared__ float kp_s[P_ * D_];
    __shared__ float vp_s[P_ * D_];
    __shared__ float qi_s[D_];
    int bh = blockIdx.y;
    int b = bh >> 3, h = bh & 7;
    int n = blockIdx.x * 128 + threadIdx.x;
    const float4* kp4 = (const float4*)(g_kp + bh * (P_ * D_));
    const float4* vp4 = (const float4*)(g_vp + bh * (P_ * D_));
    for (int i = threadIdx.x; i < (P_ * D_) / 4; i += 128) {
        ((float4*)kp_s)[i] = kp4[i];
        ((float4*)vp_s)[i] = vp4[i];
    }
    if (threadIdx.x < 64) qi_s[threadIdx.x] = g_qinv[bh * 64 + threadIdx.x];
    __syncthreads();
    float t2 = temp2[h];
    const float* qrow = g_qkv + (size_t)b * (N_ * 1536) + (size_t)n * 1536 + h * 64;

    float q[64];
#pragma unroll
    for (int d = 0; d < 64; d++) q[d] = qrow[d] * qi_s[d];

    float s[64];
    float mx = -1e30f;
#pragma unroll
    for (int p = 0; p < 64; p++) {
        float acc = 0.f;
#pragma unroll
        for (int d = 0; d < 64; d += 4) {
            float4 k4 = *(const float4*)&kp_s[p * 64 + d];
            acc += q[d] * k4.x + q[d + 1] * k4.y + q[d + 2] * k4.z + q[d + 3] * k4.w;
        }
        s[p] = acc * t2;
        mx = fmaxf(mx, s[p]);
    }
    float sum = 0.f;
#pragma unroll
    for (int p = 0; p < 64; p++) {
        s[p] = __expf(s[p] - mx);
        sum += s[p];
    }
    float inv = 1.f / sum;

    float o[64];
#pragma unroll
    for (int d = 0; d < 64; d++) o[d] = 0.f;
#pragma unroll
    for (int p = 0; p < 64; p++) {
        float sp = s[p] * inv;
#pragma unroll
        for (int d = 0; d < 64; d += 4) {
            float4 v4 = *(const float4*)&vp_s[p * 64 + d];
            o[d] += sp * v4.x;
            o[d + 1] += sp * v4.y;
            o[d + 2] += sp * v4.z;
            o[d + 3] += sp * v4.w;
        }
    }
    int rbase = h * 8 + (n >> 9);
    int col = n & 511;
    size_t boff = (size_t)b * (N_ * C_);
#pragma unroll
    for (int d = 0; d < 64; d++) {
        __nv_bfloat16 hh, ll;
        split_bf16(o[d], hh, ll);
        size_t idx = boff + (size_t)(d * 64 + rbase) * 512 + col;
        g_xsah[idx] = hh;
        g_xsal[idx] = ll;
    }
}

// ================= K7: M^T[b,j,k] = (attn^T @ w_o2^T)^T, bf16 hi/lo out =================
#define SP2 132
template <bool AT, bool BT>
__device__ __forceinline__ void gemm128x128(
    const float* __restrict__ A, int lda, const float* __restrict__ B, int ldb,
    int K, float (&acc)[8][8], float (*As)[8][SP2], float (*Bs)[8][SP2]) {
    int tid = threadIdx.x;
    int tx = tid & 15, ty = tid >> 4;
    int rowT = tid >> 1, kqT = (tid & 1) * 4;
    int krD = tid >> 5, mqD = (tid & 31) * 4;
    float4 ra, rb;
    auto loadA = [&](int k0) {
        if (AT) ra = *(const float4*)&A[(size_t)rowT * lda + k0 + kqT];
        else    ra = *(const float4*)&A[(size_t)(k0 + krD) * lda + mqD];
    };
    auto loadB = [&](int k0) {
        if (BT) rb = *(const float4*)&B[(size_t)rowT * ldb + k0 + kqT];
        else    rb = *(const float4*)&B[(size_t)(k0 + krD) * ldb + mqD];
    };
    auto storeA = [&](int buf) {
        if (AT) {
            As[buf][kqT + 0][rowT] = ra.x; As[buf][kqT + 1][rowT] = ra.y;
            As[buf][kqT + 2][rowT] = ra.z; As[buf][kqT + 3][rowT] = ra.w;
        } else *(float4*)&As[buf][krD][mqD] = ra;
    };
    auto storeB = [&](int buf) {
        if (BT) {
            Bs[buf][kqT + 0][rowT] = rb.x; Bs[buf][kqT + 1][rowT] = rb.y;
            Bs[buf][kqT + 2][rowT] = rb.z; Bs[buf][kqT + 3][rowT] = rb.w;
        } else *(float4*)&Bs[buf][krD][mqD] = rb;
    };
    loadA(0); loadB(0); storeA(0); storeB(0);
    __syncthreads();
    int nk = K >> 3;
    for (int kt = 0; kt < nk; kt++) {
        int cur = kt & 1;
        if (kt + 1 < nk) { loadA((kt + 1) << 3); loadB((kt + 1) << 3); }
#pragma unroll
        for (int kk = 0; kk < 8; kk++) {
            float4 a0 = *(const float4*)&As[cur][kk][ty * 8];
            float4 a1 = *(const float4*)&As[cur][kk][ty * 8 + 4];
            float4 b0 = *(const float4*)&Bs[cur][kk][tx * 8];
            float4 b1 = *(const float4*)&Bs[cur][kk][tx * 8 + 4];
            float a[8] = {a0.x, a0.y, a0.z, a0.w, a1.x, a1.y, a1.z, a1.w};
            float b[8] = {b0.x, b0.y, b0.z, b0.w, b1.x, b1.y, b1.z, b1.w};
#pragma unroll
            for (int i = 0; i < 8; i++)
#pragma unroll
                for (int j = 0; j < 8; j++) acc[i][j] += a[i] * b[j];
        }
        if (kt + 1 < nk) { storeA(cur ^ 1); storeB(cur ^ 1); __syncthreads(); }
    }
}

__global__ __launch_bounds__(256) void k_M(const float* __restrict__ w_o2) {
    __shared__ float As[2][8][SP2];
    __shared__ float Bs[2][8][SP2];
    int b = blockIdx.z;
    int m0 = blockIdx.y * 128;  // c'
    int n0 = blockIdx.x * 128;  // j (only 2 tiles: 256 cols)
    const float* A = g_gram + (size_t)b * (512 * 512);
    float acc[8][8] = {};
    gemm128x128<false, true>(A + m0, 512, w_o2 + (size_t)n0 * 512, 512, 512, acc, As, Bs);
    int tx = threadIdx.x & 15, ty = threadIdx.x >> 4;
#pragma unroll
    for (int i = 0; i < 8; i++) {
        int k = m0 + ty * 8 + i;
#pragma unroll
        for (int jj = 0; jj < 8; jj++) {
            int j = n0 + tx * 8 + jj;
            __nv_bfloat16 hh, ll;
            split_bf16(acc[i][jj], hh, ll);
            size_t idx = ((size_t)b * 256 + j) * 512 + k;
            g_Mh[idx] = hh;
            g_Ml[idx] = ll;
        }
    }
}

// ================= launch =================
extern "C" void kernel_launch(void* const* d_in, const int* in_sizes, int n_in,
                              void* d_out, int out_size) {
    const float* x      = (const float*)d_in[0];
    const float* w_qkv  = (const float*)d_in[1];
    const float* w_e    = (const float*)d_in[2];
    const float* b_e    = (const float*)d_in[3];
    const float* temp   = (const float*)d_in[4];
    const float* temp2  = (const float*)d_in[5];
    const float* w_o1   = (const float*)d_in[6];
    const float* b_o1   = (const float*)d_in[7];
    const float* w_o2   = (const float*)d_in[8];
    const float* b_o2   = (const float*)d_in[9];
    float* out = (float*)d_out;

    // bf16 hi/lo conversions (globals referenced inside kernels only)
    c_split_x<<<(B_ * N_ * C_) / 1024, 256>>>(x);
    c_split_wq<<<(3 * C_ * C_) / 1024, 256>>>(w_qkv);
    c_split_wo1<<<((C_ / 2) * C_) / 1024, 256>>>(w_o1);

    k_qkv_w<<<dim3(12, 256), 256>>>();            // 51.5 GF (x3 passes)
    k_qnorm<<<64, 256>>>();
    k_proj<<<dim3(64, 2), 256>>>(w_e, b_e);
    k_gram_w<<<dim3(4, 4, 8), 256>>>();           // 17.2 GF
    k_softmax512<<<B_ * C_, 256>>>(temp);
    k_sa<<<dim3(32, 64), 128>>>(temp2);
    k_M<<<dim3(2, 4, 8), 256>>>(w_o2);            // j has 2 tiles (256 cols)
    k_out1_w<<<dim3(2, 256), 256>>>(out);         // 8.6 GF
    k_out2_w<<<dim3(2, 256), 256>>>(out);         // 8.6 GF
    k_bias<<<(B_ * N_ * C_) / 1024, 256>>>(b_o1, b_o2, out);
}

// round 10
// speedup vs baseline: 1.6929x; 1.1140x over previous
#include <cuda_runtime.h>
#include <cuda_bf16.h>
#include <mma.h>
#include <type_traits>
#include <math.h>
#include <cstdint>

using namespace nvcuda;

// Problem constants
#define B_ 8
#define N_ 4096
#define C_ 512
#define H_ 8
#define P_ 64
#define D_ 64

// ---------------- scratch (device globals; no runtime allocation) ----------------
// NOTE: device globals must ONLY be referenced from device code (GB300 ATS
// makes host-shadow writes silently succeed into host memory otherwise).
__device__ float g_qkv[B_ * N_ * 3 * C_];      // [b, n, 1536] fp32
__device__ float g_qinv[B_ * H_ * D_];
__device__ float g_kp[B_ * H_ * P_ * D_];
__device__ float g_vp[B_ * H_ * P_ * D_];
__device__ float g_gram[B_ * C_ * C_];         // softmaxed in place
__device__ __nv_bfloat16 g_xh[B_ * N_ * C_],  g_xl[B_ * N_ * C_];    // x [row, 512]
__device__ __nv_bfloat16 g_wqh[3 * C_ * C_],  g_wql[3 * C_ * C_];    // w_qkv [n, 512]
__device__ __nv_bfloat16 g_wo1h[(C_/2) * C_], g_wo1l[(C_/2) * C_];   // w_o1 [n, 512]
__device__ __nv_bfloat16 g_xsah[B_ * N_ * C_], g_xsal[B_ * N_ * C_]; // scrambled x_sa
__device__ __nv_bfloat16 g_Mh[B_ * (C_/2) * C_], g_Ml[B_ * (C_/2) * C_]; // M^T [b,j,k]

__device__ __forceinline__ void split_bf16(float x, __nv_bfloat16& h, __nv_bfloat16& l) {
    h = __float2bfloat16(x);
    l = __float2bfloat16(x - __bfloat162float(h));
}

// =====================================================================
// wmma bf16 3-pass GEMM, 64x128 CTA tile, 128 threads (4 warps, warp
// tile 64x32). SMEM-staged operands (proven r9 pattern), K chunks of 32.
// Small CTA => 2 CTAs/SM resident (reg-bound), cross-CTA barrier overlap.
//   matrix_a row: A[m][k] at A[m*lda+k]   col: A[m][k] at A[k*lda+m]
//   matrix_b col: B[k][n] at B[n*ldb+k]   row: B[k][n] at B[k*ldb+n]
// =====================================================================
#define RSTR 40
#define KSTR 136
#define KSTRA 72

template <bool ACol, bool BCol>
__device__ __forceinline__ void gemm_wmma2(
    const __nv_bfloat16* __restrict__ Ah, const __nv_bfloat16* __restrict__ Al, int lda,
    const __nv_bfloat16* __restrict__ Bh, const __nv_bfloat16* __restrict__ Bl, int ldb,
    int K, float* __restrict__ Cp, int ldc) {
    using ALay = typename std::conditional<ACol, wmma::col_major, wmma::row_major>::type;
    using BLay = typename std::conditional<BCol, wmma::col_major, wmma::row_major>::type;
    __shared__ __nv_bfloat16 sAh[ACol ? 32 * KSTRA : 64 * RSTR];
    __shared__ __nv_bfloat16 sAl[ACol ? 32 * KSTRA : 64 * RSTR];
    __shared__ __nv_bfloat16 sBh[BCol ? 128 * RSTR : 32 * KSTR];
    __shared__ __nv_bfloat16 sBl[BCol ? 128 * RSTR : 32 * KSTR];

    int tid = threadIdx.x;
    int wn = tid >> 5;   // 4 warps across N

    uint4 rAh[2], rAl[2], rBh[4], rBl[4];

    auto LD = [&](int k0) {
#pragma unroll
        for (int u = 0; u < 2; u++) {        // A: 64x32 or 32x64 = 256 uint4
            int idx = u * 128 + tid;
            size_t o;
            if (ACol) { int kr = idx >> 3, q = idx & 7; o = (size_t)(k0 + kr) * lda + q * 8; }
            else      { int row = idx >> 2, q = idx & 3; o = (size_t)row * lda + k0 + q * 8; }
            rAh[u] = *(const uint4*)(Ah + o);
            rAl[u] = *(const uint4*)(Al + o);
        }
#pragma unroll
        for (int u = 0; u < 4; u++) {        // B: 128x32 or 32x128 = 512 uint4
            int idx = u * 128 + tid;
            size_t o;
            if (BCol) { int row = idx >> 2, q = idx & 3; o = (size_t)row * ldb + k0 + q * 8; }
            else      { int kr = idx >> 4, q = idx & 15; o = (size_t)(k0 + kr) * ldb + q * 8; }
            rBh[u] = *(const uint4*)(Bh + o);
            rBl[u] = *(const uint4*)(Bl + o);
        }
    };
    auto ST = [&]() {
#pragma unroll
        for (int u = 0; u < 2; u++) {
            int idx = u * 128 + tid;
            int so;
            if (ACol) { int kr = idx >> 3, q = idx & 7; so = kr * KSTRA + q * 8; }
            else      { int row = idx >> 2, q = idx & 3; so = row * RSTR + q * 8; }
            *(uint4*)(sAh + so) = rAh[u];
            *(uint4*)(sAl + so) = rAl[u];
        }
#pragma unroll
        for (int u = 0; u < 4; u++) {
            int idx = u * 128 + tid;
            int so;
            if (BCol) { int row = idx >> 2, q = idx & 3; so = row * RSTR + q * 8; }
            else      { int kr = idx >> 4, q = idx & 15; so = kr * KSTR + q * 8; }
            *(uint4*)(sBh + so) = rBh[u];
            *(uint4*)(sBl + so) = rBl[u];
        }
    };

    wmma::fragment<wmma::accumulator, 16, 16, 16, float> acc[4][2];
#pragma unroll
    for (int i = 0; i < 4; i++)
#pragma unroll
        for (int j = 0; j < 2; j++) wmma::fill_fragment(acc[i][j], 0.0f);

    LD(0); ST();
    __syncthreads();

    int nk = K >> 5;
    for (int kt = 0; kt < nk; kt++) {
        if (kt + 1 < nk) LD((kt + 1) << 5);
#pragma unroll
        for (int kk = 0; kk < 32; kk += 16) {
            wmma::fragment<wmma::matrix_a, 16, 16, 16, __nv_bfloat16, ALay> ah[4], al[4];
            wmma::fragment<wmma::matrix_b, 16, 16, 16, __nv_bfloat16, BLay> bh[2], bl[2];
#pragma unroll
            for (int i = 0; i < 4; i++) {
                int m = i * 16;
                if (ACol) {
                    wmma::load_matrix_sync(ah[i], sAh + kk * KSTRA + m, KSTRA);
                    wmma::load_matrix_sync(al[i], sAl + kk * KSTRA + m, KSTRA);
                } else {
                    wmma::load_matrix_sync(ah[i], sAh + m * RSTR + kk, RSTR);
                    wmma::load_matrix_sync(al[i], sAl + m * RSTR + kk, RSTR);
                }
            }
#pragma unroll
            for (int j = 0; j < 2; j++) {
                int n = wn * 32 + j * 16;
                if (BCol) {
                    wmma::load_matrix_sync(bh[j], sBh + n * RSTR + kk, RSTR);
                    wmma::load_matrix_sync(bl[j], sBl + n * RSTR + kk, RSTR);
                } else {
                    wmma::load_matrix_sync(bh[j], sBh + kk * KSTR + n, KSTR);
                    wmma::load_matrix_sync(bl[j], sBl + kk * KSTR + n, KSTR);
                }
            }
#pragma unroll
            for (int i = 0; i < 4; i++)
#pragma unroll
                for (int j = 0; j < 2; j++) {
                    wmma::mma_sync(acc[i][j], ah[i], bh[j], acc[i][j]);
                    wmma::mma_sync(acc[i][j], ah[i], bl[j], acc[i][j]);
                    wmma::mma_sync(acc[i][j], al[i], bh[j], acc[i][j]);
                }
        }
        if (kt + 1 < nk) {
            __syncthreads();
            ST();
            __syncthreads();
        }
    }
#pragma unroll
    for (int i = 0; i < 4; i++)
#pragma unroll
        for (int j = 0; j < 2; j++) {
            int m = i * 16, n = wn * 32 + j * 16;
            wmma::store_matrix_sync(Cp + (size_t)m * ldc + n, acc[i][j], ldc,
                                    wmma::mem_row_major);
        }
}

// ================= K1: qkv = x @ w_qkv^T =================
__global__ __launch_bounds__(128) void k_qkv_w() {
    int m0 = blockIdx.y * 64, n0 = blockIdx.x * 128;
    gemm_wmma2<false, true>(g_xh + (size_t)m0 * 512, g_xl + (size_t)m0 * 512, 512,
                            g_wqh + (size_t)n0 * 512, g_wql + (size_t)n0 * 512, 512,
                            512, g_qkv + (size_t)m0 * 1536 + n0, 1536);
}

// ================= K4: Gram[b] = X^T X (A col-major view of x) =================
__global__ __launch_bounds__(128) void k_gram_w() {
    int b = blockIdx.z;
    int c10 = blockIdx.y * 64, c20 = blockIdx.x * 128;
    const __nv_bfloat16* xh = g_xh + (size_t)b * N_ * C_;
    const __nv_bfloat16* xl = g_xl + (size_t)b * N_ * C_;
    gemm_wmma2<true, false>(xh + c10, xl + c10, 512, xh + c20, xl + c20, 512,
                            N_, g_gram + ((size_t)(b * 512 + c10)) * 512 + c20, 512);
}

// ================= K8: out[:, :256] = xsa @ w_o1^T =================
__global__ __launch_bounds__(128) void k_out1_w(float* __restrict__ out) {
    int m0 = blockIdx.y * 64, n0 = blockIdx.x * 128;
    gemm_wmma2<false, true>(g_xsah + (size_t)m0 * 512, g_xsal + (size_t)m0 * 512, 512,
                            g_wo1h + (size_t)n0 * 512, g_wo1l + (size_t)n0 * 512, 512,
                            512, out + (size_t)m0 * 512 + n0, 512);
}

// ================= K9: out[:, 256:] = x @ M[b] =================
__global__ __launch_bounds__(128) void k_out2_w(float* __restrict__ out) {
    int m0 = blockIdx.y * 64, n0 = blockIdx.x * 128;
    int b = m0 >> 12;
    gemm_wmma2<false, true>(g_xh + (size_t)m0 * 512, g_xl + (size_t)m0 * 512, 512,
                            g_Mh + ((size_t)b * 256 + n0) * 512,
                            g_Ml + ((size_t)b * 256 + n0) * 512, 512,
                            512, out + (size_t)m0 * 512 + 256 + n0, 512);
}

// ================= K3: kp/vp via wmma, split-on-stage from fp32 =============
// Per (b, kv, h): C[64p, 64d] = w_e[64,4096] @ KV_head[4096,64] + b_e.
// Stages fp32 w_e and g_qkv K/V slices, converting to bf16 hi/lo in regs.
__device__ __forceinline__ void pack4(float4 v, __nv_bfloat16* h, __nv_bfloat16* l) {
    __nv_bfloat16 hh[4], ll[4];
    split_bf16(v.x, hh[0], ll[0]); split_bf16(v.y, hh[1], ll[1]);
    split_bf16(v.z, hh[2], ll[2]); split_bf16(v.w, hh[3], ll[3]);
    *(uint2*)h = *(uint2*)hh;
    *(uint2*)l = *(uint2*)ll;
}

__global__ __launch_bounds__(128) void k_proj_w(const float* __restrict__ w_e,
                                                const float* __restrict__ b_e) {
    __shared__ __nv_bfloat16 sAh[64 * RSTR], sAl[64 * RSTR];   // w_e tile 64x32
    __shared__ __nv_bfloat16 sBh[32 * KSTRA], sBl[32 * KSTRA]; // KV tile 32x64
    int tid = threadIdx.x;
    int wn = tid >> 5;
    int h = blockIdx.x;
    int b = blockIdx.y >> 1, kv = blockIdx.y & 1;
    const float* Bp = g_qkv + (size_t)b * N_ * 1536 + 512 + kv * 512 + h * 64;

    float4 rA[4], rB[4];
    auto LD = [&](int k0) {
#pragma unroll
        for (int u = 0; u < 4; u++) {
            int idx = u * 128 + tid;
            int rowA = idx >> 3, qA = idx & 7;      // 64 rows x 8 float4
            rA[u] = *(const float4*)&w_e[(size_t)rowA * N_ + k0 + qA * 4];
            int krB = idx >> 4, qB = idx & 15;      // 32 k-rows x 16 float4
            rB[u] = *(const float4*)&Bp[(size_t)(k0 + krB) * 1536 + qB * 4];
        }
    };
    auto ST = [&]() {
#pragma unroll
        for (int u = 0; u < 4; u++) {
            int idx = u * 128 + tid;
            int rowA = idx >> 3, qA = idx & 7;
            pack4(rA[u], sAh + rowA * RSTR + qA * 4, sAl + rowA * RSTR + qA * 4);
            int krB = idx >> 4, qB = idx & 15;
            pack4(rB[u], sBh + krB * KSTRA + qB * 4, sBl + krB * KSTRA + qB * 4);
        }
    };

    wmma::fragment<wmma::accumulator, 16, 16, 16, float> acc[4];
#pragma unroll
    for (int i = 0; i < 4; i++) wmma::fill_fragment(acc[i], 0.0f);

    LD(0); ST();
    __syncthreads();

    int nk = N_ >> 5;   // 128 chunks
    for (int kt = 0; kt < nk; kt++) {
        if (kt + 1 < nk) LD((kt + 1) << 5);
#pragma unroll
        for (int kk = 0; kk < 32; kk += 16) {
            wmma::fragment<wmma::matrix_a, 16, 16, 16, __nv_bfloat16, wmma::row_major> ah[4], al[4];
            wmma::fragment<wmma::matrix_b, 16, 16, 16, __nv_bfloat16, wmma::row_major> bh, bl;
#pragma unroll
            for (int i = 0; i < 4; i++) {
                wmma::load_matrix_sync(ah[i], sAh + i * 16 * RSTR + kk, RSTR);
                wmma::load_matrix_sync(al[i], sAl + i * 16 * RSTR + kk, RSTR);
            }
            wmma::load_matrix_sync(bh, sBh + kk * KSTRA + wn * 16, KSTRA);
            wmma::load_matrix_sync(bl, sBl + kk * KSTRA + wn * 16, KSTRA);
#pragma unroll
            for (int i = 0; i < 4; i++) {
                wmma::mma_sync(acc[i], ah[i], bh, acc[i]);
                wmma::mma_sync(acc[i], ah[i], bl, acc[i]);
                wmma::mma_sync(acc[i], al[i], bh, acc[i]);
            }
        }
        if (kt + 1 < nk) {
            __syncthreads();
            ST();
            __syncthreads();
        }
    }
    float* dst = (kv ? g_vp : g_kp) + (size_t)(b * 8 + h) * (P_ * D_);
#pragma unroll
    for (int i = 0; i < 4; i++)
        wmma::store_matrix_sync(dst + i * 16 * 64 + wn * 16, acc[i], 64,
                                wmma::mem_row_major);
    __syncthreads();   // orders global stores within CTA
    for (int idx = tid; idx < P_ * D_; idx += 128) dst[idx] += b_e[idx >> 6];
}

// ================= bias epilogue: out[r][c] += b_o1/b_o2 =================
__global__ __launch_bounds__(256) void k_bias(const float* __restrict__ b_o1,
                                              const float* __restrict__ b_o2,
                                              float* __restrict__ out) {
    size_t i = ((size_t)blockIdx.x * 256 + threadIdx.x) * 4;
    int c = (int)(i & 511);
    const float* bias = (c < 256) ? (b_o1 + c) : (b_o2 + c - 256);
    float4 v = *(float4*)(out + i);
    float4 bb = *(const float4*)bias;
    v.x += bb.x; v.y += bb.y; v.z += bb.z; v.w += bb.w;
    *(float4*)(out + i) = v;
}

// ================= conversions (destinations referenced in DEVICE code) =====
__device__ __forceinline__ void split4_to(const float* __restrict__ s,
                                          __nv_bfloat16* __restrict__ h,
                                          __nv_bfloat16* __restrict__ l, size_t i) {
    float4 v = *(const float4*)(s + i);
    __nv_bfloat16 hh[4], ll[4];
    split_bf16(v.x, hh[0], ll[0]); split_bf16(v.y, hh[1], ll[1]);
    split_bf16(v.z, hh[2], ll[2]); split_bf16(v.w, hh[3], ll[3]);
    *(uint2*)(h + i) = *(uint2*)hh;
    *(uint2*)(l + i) = *(uint2*)ll;
}

__global__ void c_split_x(const float* __restrict__ s) {
    size_t i = ((size_t)blockIdx.x * 256 + threadIdx.x) * 4;
    split4_to(s, g_xh, g_xl, i);
}
__global__ void c_split_wq(const float* __restrict__ s) {
    size_t i = ((size_t)blockIdx.x * 256 + threadIdx.x) * 4;
    split4_to(s, g_wqh, g_wql, i);
}
__global__ void c_split_wo1(const float* __restrict__ s) {
    size_t i = ((size_t)blockIdx.x * 256 + threadIdx.x) * 4;
    split4_to(s, g_wo1h, g_wo1l, i);
}

// ================= K2: q token-axis L2 norm inverses =================
__global__ __launch_bounds__(256) void k_qnorm() {
    int bh = blockIdx.x;
    int b = bh >> 3, h = bh & 7;
    int tid = threadIdx.x;
    int d = tid & 63, sl = tid >> 6;
    const float* q = g_qkv + (size_t)b * (N_ * 1536) + h * 64 + d;
    float s = 0.f;
    for (int n = sl; n < N_; n += 4) {
        float v = q[(size_t)n * 1536];
        s += v * v;
    }
    __shared__ float red[256];
    red[tid] = s;
    __syncthreads();
    if (sl == 0) {
        float tot = red[d] + red[d + 64] + red[d + 128] + red[d + 192];
        g_qinv[bh * 64 + d] = 1.f / fmaxf(sqrtf(tot), 1e-12f);
    }
}

// ================= K5: row softmax of Gram * temperature =================
__global__ __launch_bounds__(256) void k_softmax512(const float* __restrict__ temp) {
    int row = blockIdx.x;
    float t = temp[0];
    float* p = g_gram + (size_t)row * 512;
    int tid = threadIdx.x;
    __shared__ float red[256];
    float v0 = p[tid] * t, v1 = p[tid + 256] * t;
    red[tid] = fmaxf(v0, v1);
    __syncthreads();
    for (int s = 128; s > 0; s >>= 1) {
        if (tid < s) red[tid] = fmaxf(red[tid], red[tid + s]);
        __syncthreads();
    }
    float mx = red[0];
    __syncthreads();
    float e0 = __expf(v0 - mx), e1 = __expf(v1 - mx);
    red[tid] = e0 + e1;
    __syncthreads();
    for (int s = 128; s > 0; s >>= 1) {
        if (tid < s) red[tid] += red[tid + s];
        __syncthreads();
    }
    float inv = 1.f / red[0];
    p[tid] = e0 * inv;
    p[tid + 256] = e1 * inv;
}

// ================= K6: fused spatial attention (writes bf16 hi/lo) =================
__global__ __launch_bounds__(128) void k_sa(const float* __restrict__ temp2) {
    __shared__ float kp_s[P_ * D_];
    __shared__ float vp_s[P_ * D_];
    __shared__ float qi_s[D_];
    int bh = blockIdx.y;
    int b = bh >> 3, h = bh & 7;
    int n = blockIdx.x * 128 + threadIdx.x;
    const float4* kp4 = (const float4*)(g_kp + bh * (P_ * D_));
    const float4* vp4 = (const float4*)(g_vp + bh * (P_ * D_));
    for (int i = threadIdx.x; i < (P_ * D_) / 4; i += 128) {
        ((float4*)kp_s)[i] = kp4[i];
        ((float4*)vp_s)[i] = vp4[i];
    }
    if (threadIdx.x < 64) qi_s[threadIdx.x] = g_qinv[bh * 64 + threadIdx.x];
    __syncthreads();
    float t2 = temp2[h];
    const float* qrow = g_qkv + (size_t)b * (N_ * 1536) + (size_t)n * 1536 + h * 64;

    float q[64];
#pragma unroll
    for (int d = 0; d < 64; d++) q[d] = qrow[d] * qi_s[d];

    float s[64];
    float mx = -1e30f;
#pragma unroll
    for (int p = 0; p < 64; p++) {
        float acc = 0.f;
#pragma unroll
        for (int d = 0; d < 64; d += 4) {
            float4 k4 = *(const float4*)&kp_s[p * 64 + d];
            acc += q[d] * k4.x + q[d + 1] * k4.y + q[d + 2] * k4.z + q[d + 3] * k4.w;
        }
        s[p] = acc * t2;
        mx = fmaxf(mx, s[p]);
    }
    float sum = 0.f;
#pragma unroll
    for (int p = 0; p < 64; p++) {
        s[p] = __expf(s[p] - mx);
        sum += s[p];
    }
    float inv = 1.f / sum;

    float o[64];
#pragma unroll
    for (int d = 0; d < 64; d++) o[d] = 0.f;
#pragma unroll
    for (int p = 0; p < 64; p++) {
        float sp = s[p] * inv;
#pragma unroll
        for (int d = 0; d < 64; d += 4) {
            float4 v4 = *(const float4*)&vp_s[p * 64 + d];
            o[d] += sp * v4.x;
            o[d + 1] += sp * v4.y;
            o[d + 2] += sp * v4.z;
            o[d + 3] += sp * v4.w;
        }
    }
    int rbase = h * 8 + (n >> 9);
    int col = n & 511;
    size_t boff = (size_t)b * (N_ * C_);
#pragma unroll
    for (int d = 0; d < 64; d++) {
        __nv_bfloat16 hh, ll;
        split_bf16(o[d], hh, ll);
        size_t idx = boff + (size_t)(d * 64 + rbase) * 512 + col;
        g_xsah[idx] = hh;
        g_xsal[idx] = ll;
    }
}

// ================= K7: M^T[b,j,k] = (attn^T @ w_o2^T)^T, bf16 hi/lo out =================
#define SP2 132
template <bool AT, bool BT>
__device__ __forceinline__ void gemm128x128(
    const float* __restrict__ A, int lda, const float* __restrict__ B, int ldb,
    int K, float (&acc)[8][8], float (*As)[8][SP2], float (*Bs)[8][SP2]) {
    int tid = threadIdx.x;
    int tx = tid & 15, ty = tid >> 4;
    int rowT = tid >> 1, kqT = (tid & 1) * 4;
    int krD = tid >> 5, mqD = (tid & 31) * 4;
    float4 ra, rb;
    auto loadA = [&](int k0) {
        if (AT) ra = *(const float4*)&A[(size_t)rowT * lda + k0 + kqT];
        else    ra = *(const float4*)&A[(size_t)(k0 + krD) * lda + mqD];
    };
    auto loadB = [&](int k0) {
        if (BT) rb = *(const float4*)&B[(size_t)rowT * ldb + k0 + kqT];
        else    rb = *(const float4*)&B[(size_t)(k0 + krD) * ldb + mqD];
    };
    auto storeA = [&](int buf) {
        if (AT) {
            As[buf][kqT + 0][rowT] = ra.x; As[buf][kqT + 1][rowT] = ra.y;
            As[buf][kqT + 2][rowT] = ra.z; As[buf][kqT + 3][rowT] = ra.w;
        } else *(float4*)&As[buf][krD][mqD] = ra;
    };
    auto storeB = [&](int buf) {
        if (BT) {
            Bs[buf][kqT + 0][rowT] = rb.x; Bs[buf][kqT + 1][rowT] = rb.y;
            Bs[buf][kqT + 2][rowT] = rb.z; Bs[buf][kqT + 3][rowT] = rb.w;
        } else *(float4*)&Bs[buf][krD][mqD] = rb;
    };
    loadA(0); loadB(0); storeA(0); storeB(0);
    __syncthreads();
    int nk = K >> 3;
    for (int kt = 0; kt < nk; kt++) {
        int cur = kt & 1;
        if (kt + 1 < nk) { loadA((kt + 1) << 3); loadB((kt + 1) << 3); }
#pragma unroll
        for (int kk = 0; kk < 8; kk++) {
            float4 a0 = *(const float4*)&As[cur][kk][ty * 8];
            float4 a1 = *(const float4*)&As[cur][kk][ty * 8 + 4];
            float4 b0 = *(const float4*)&Bs[cur][kk][tx * 8];
            float4 b1 = *(const float4*)&Bs[cur][kk][tx * 8 + 4];
            float a[8] = {a0.x, a0.y, a0.z, a0.w, a1.x, a1.y, a1.z, a1.w};
            float b[8] = {b0.x, b0.y, b0.z, b0.w, b1.x, b1.y, b1.z, b1.w};
#pragma unroll
            for (int i = 0; i < 8; i++)
#pragma unroll
                for (int j = 0; j < 8; j++) acc[i][j] += a[i] * b[j];
        }
        if (kt + 1 < nk) { storeA(cur ^ 1); storeB(cur ^ 1); __syncthreads(); }
    }
}

__global__ __launch_bounds__(256) void k_M(const float* __restrict__ w_o2) {
    __shared__ float As[2][8][SP2];
    __shared__ float Bs[2][8][SP2];
    int b = blockIdx.z;
    int m0 = blockIdx.y * 128;  // c'
    int n0 = blockIdx.x * 128;  // j (only 2 tiles: 256 cols)
    const float* A = g_gram + (size_t)b * (512 * 512);
    float acc[8][8] = {};
    gemm128x128<false, true>(A + m0, 512, w_o2 + (size_t)n0 * 512, 512, 512, acc, As, Bs);
    int tx = threadIdx.x & 15, ty = threadIdx.x >> 4;
#pragma unroll
    for (int i = 0; i < 8; i++) {
        int k = m0 + ty * 8 + i;
#pragma unroll
        for (int jj = 0; jj < 8; jj++) {
            int j = n0 + tx * 8 + jj;
            __nv_bfloat16 hh, ll;
            split_bf16(acc[i][jj], hh, ll);
            size_t idx = ((size_t)b * 256 + j) * 512 + k;
            g_Mh[idx] = hh;
            g_Ml[idx] = ll;
        }
    }
}

// ================= launch =================
extern "C" void kernel_launch(void* const* d_in, const int* in_sizes, int n_in,
                              void* d_out, int out_size) {
    const float* x      = (const float*)d_in[0];
    const float* w_qkv  = (const float*)d_in[1];
    const float* w_e    = (const float*)d_in[2];
    const float* b_e    = (const float*)d_in[3];
    const float* temp   = (const float*)d_in[4];
    const float* temp2  = (const float*)d_in[5];
    const float* w_o1   = (const float*)d_in[6];
    const float* b_o1   = (const float*)d_in[7];
    const float* w_o2   = (const float*)d_in[8];
    const float* b_o2   = (const float*)d_in[9];
    float* out = (float*)d_out;

    // bf16 hi/lo conversions (globals referenced inside kernels only)
    c_split_x<<<(B_ * N_ * C_) / 1024, 256>>>(x);
    c_split_wq<<<(3 * C_ * C_) / 1024, 256>>>(w_qkv);
    c_split_wo1<<<((C_ / 2) * C_) / 1024, 256>>>(w_o1);

    k_qkv_w<<<dim3(12, 512), 128>>>();            // 51.5 GF (x3 passes)
    k_qnorm<<<64, 256>>>();
    k_proj_w<<<dim3(8, 16), 128>>>(w_e, b_e);     // wmma, split-on-stage
    k_gram_w<<<dim3(4, 8, 8), 128>>>();           // 17.2 GF
    k_softmax512<<<B_ * C_, 256>>>(temp);
    k_sa<<<dim3(32, 64), 128>>>(temp2);
    k_M<<<dim3(2, 4, 8), 256>>>(w_o2);            // j has 2 tiles (256 cols)
    k_out1_w<<<dim3(2, 512), 128>>>(out);         // 8.6 GF
    k_out2_w<<<dim3(2, 512), 128>>>(out);         // 8.6 GF
    k_bias<<<(B_ * N_ * C_) / 1024, 256>>>(b_o1, b_o2, out);
}

// round 11
// speedup vs baseline: 1.8672x; 1.1029x over previous
#include <cuda_runtime.h>
#include <cuda_bf16.h>
#include <mma.h>
#include <type_traits>
#include <math.h>
#include <cstdint>

using namespace nvcuda;

// Problem constants
#define B_ 8
#define N_ 4096
#define C_ 512
#define H_ 8
#define P_ 64
#define D_ 64

// ---------------- scratch (device globals; no runtime allocation) ----------------
// NOTE: device globals must ONLY be referenced from device code (GB300 ATS
// makes host-shadow writes silently succeed into host memory otherwise).
__device__ float g_qkv[B_ * N_ * 3 * C_];      // [b, n, 1536] fp32
__device__ float g_qinv[B_ * H_ * D_];
__device__ float g_kp[B_ * H_ * P_ * D_];
__device__ float g_vp[B_ * H_ * P_ * D_];
__device__ float g_gram[B_ * C_ * C_];         // softmaxed in place
__device__ __nv_bfloat16 g_xh[B_ * N_ * C_],  g_xl[B_ * N_ * C_];    // x [row, 512]
__device__ __nv_bfloat16 g_wqh[3 * C_ * C_],  g_wql[3 * C_ * C_];    // w_qkv [n, 512]
__device__ __nv_bfloat16 g_wo1h[(C_/2) * C_], g_wo1l[(C_/2) * C_];   // w_o1 [n, 512]
__device__ __nv_bfloat16 g_xsah[B_ * N_ * C_], g_xsal[B_ * N_ * C_]; // scrambled x_sa
__device__ __nv_bfloat16 g_Mh[B_ * (C_/2) * C_], g_Ml[B_ * (C_/2) * C_]; // M^T [b,j,k]

__device__ __forceinline__ void split_bf16(float x, __nv_bfloat16& h, __nv_bfloat16& l) {
    h = __float2bfloat16(x);
    l = __float2bfloat16(x - __bfloat162float(h));
}

__device__ __forceinline__ uint32_t smem_u32(const void* p) {
    uint32_t a;
    asm("{ .reg .u64 t; cvta.to.shared.u64 t, %1; cvt.u32.u64 %0, t; }" : "=r"(a) : "l"(p));
    return a;
}
__device__ __forceinline__ void cpasync16(uint32_t dst, const void* src) {
    asm volatile("cp.async.cg.shared.global [%0], [%1], 16;" :: "r"(dst), "l"(src));
}
#define CPCOMMIT() asm volatile("cp.async.commit_group;" ::: "memory")
#define CPWAIT(n)  asm volatile("cp.async.wait_group " #n ";" ::: "memory")

// =====================================================================
// wmma bf16 3-pass GEMM, 64x128 CTA tile, 128 threads (4 warps, warp
// tile 64x32). cp.async 2-stage double-buffered smem, K chunks of 16.
// Conflict-free padded strides: row-major 16-k tiles stride 24 elems;
// k-major tiles stride 72 (64-wide) / 136 (128-wide).
//   matrix_a row: A[m][k] at A[m*lda+k]   col: A[m][k] at A[k*lda+m]
//   matrix_b col: B[k][n] at B[n*ldb+k]   row: B[k][n] at B[k*ldb+n]
// =====================================================================
#define RM_STR 24
#define KM64 72
#define KM128 136

template <bool ACol, bool BCol>
__device__ __forceinline__ void gemm_wmma3(
    const __nv_bfloat16* __restrict__ Ah, const __nv_bfloat16* __restrict__ Al, int lda,
    const __nv_bfloat16* __restrict__ Bh, const __nv_bfloat16* __restrict__ Bl, int ldb,
    int K, float* __restrict__ Cp, int ldc) {
    using ALay = typename std::conditional<ACol, wmma::col_major, wmma::row_major>::type;
    using BLay = typename std::conditional<BCol, wmma::col_major, wmma::row_major>::type;
    constexpr int ASZ = ACol ? 16 * KM64 : 64 * RM_STR;
    constexpr int BSZ = BCol ? 128 * RM_STR : 16 * KM128;
    __shared__ __nv_bfloat16 sAh[2][ASZ], sAl[2][ASZ];
    __shared__ __nv_bfloat16 sBh[2][BSZ], sBl[2][BSZ];

    int tid = threadIdx.x;
    int wn = tid >> 5;   // 4 warps across N

    auto PF = [&](int kc, int st) {
        int k0 = kc << 4;
        uint32_t ah = smem_u32(sAh[st]), al = smem_u32(sAl[st]);
        uint32_t bhs = smem_u32(sBh[st]), bls = smem_u32(sBl[st]);
        {   // A: 128 x 16B transfers each for hi/lo
            size_t o; int so;
            if (ACol) { int kr = tid >> 3, q = tid & 7;
                        o = (size_t)(k0 + kr) * lda + q * 8; so = kr * KM64 + q * 8; }
            else      { int row = tid >> 1, q = tid & 1;
                        o = (size_t)row * lda + k0 + q * 8; so = row * RM_STR + q * 8; }
            cpasync16(ah + so * 2, Ah + o);
            cpasync16(al + so * 2, Al + o);
        }
#pragma unroll
        for (int u = 0; u < 2; u++) {   // B: 256 x 16B transfers each for hi/lo
            int idx = u * 128 + tid;
            size_t o; int so;
            if (BCol) { int row = idx >> 1, q = idx & 1;
                        o = (size_t)row * ldb + k0 + q * 8; so = row * RM_STR + q * 8; }
            else      { int kr = idx >> 4, q = idx & 15;
                        o = (size_t)(k0 + kr) * ldb + q * 8; so = kr * KM128 + q * 8; }
            cpasync16(bhs + so * 2, Bh + o);
            cpasync16(bls + so * 2, Bl + o);
        }
        CPCOMMIT();
    };

    wmma::fragment<wmma::accumulator, 16, 16, 16, float> acc[4][2];
#pragma unroll
    for (int i = 0; i < 4; i++)
#pragma unroll
        for (int j = 0; j < 2; j++) wmma::fill_fragment(acc[i][j], 0.0f);

    int nk = K >> 4;
    PF(0, 0);
    for (int kt = 0; kt < nk; kt++) {
        int st = kt & 1;
        if (kt + 1 < nk) { PF(kt + 1, st ^ 1); CPWAIT(1); }
        else             { CPWAIT(0); }
        __syncthreads();
        wmma::fragment<wmma::matrix_a, 16, 16, 16, __nv_bfloat16, ALay> ah[4], al[4];
        wmma::fragment<wmma::matrix_b, 16, 16, 16, __nv_bfloat16, BLay> bh[2], bl[2];
#pragma unroll
        for (int i = 0; i < 4; i++) {
            int m = i * 16;
            if (ACol) {
                wmma::load_matrix_sync(ah[i], sAh[st] + m, KM64);
                wmma::load_matrix_sync(al[i], sAl[st] + m, KM64);
            } else {
                wmma::load_matrix_sync(ah[i], sAh[st] + m * RM_STR, RM_STR);
                wmma::load_matrix_sync(al[i], sAl[st] + m * RM_STR, RM_STR);
            }
        }
#pragma unroll
        for (int j = 0; j < 2; j++) {
            int n = wn * 32 + j * 16;
            if (BCol) {
                wmma::load_matrix_sync(bh[j], sBh[st] + n * RM_STR, RM_STR);
                wmma::load_matrix_sync(bl[j], sBl[st] + n * RM_STR, RM_STR);
            } else {
                wmma::load_matrix_sync(bh[j], sBh[st] + n, KM128);
                wmma::load_matrix_sync(bl[j], sBl[st] + n, KM128);
            }
        }
#pragma unroll
        for (int i = 0; i < 4; i++)
#pragma unroll
            for (int j = 0; j < 2; j++) {
                wmma::mma_sync(acc[i][j], ah[i], bh[j], acc[i][j]);
                wmma::mma_sync(acc[i][j], ah[i], bl[j], acc[i][j]);
                wmma::mma_sync(acc[i][j], al[i], bh[j], acc[i][j]);
            }
        __syncthreads();   // stage consumed; safe to overwrite next iteration
    }
#pragma unroll
    for (int i = 0; i < 4; i++)
#pragma unroll
        for (int j = 0; j < 2; j++) {
            int m = i * 16, n = wn * 32 + j * 16;
            wmma::store_matrix_sync(Cp + (size_t)m * ldc + n, acc[i][j], ldc,
                                    wmma::mem_row_major);
        }
}

// ================= K1: qkv = x @ w_qkv^T =================
__global__ __launch_bounds__(128) void k_qkv_w() {
    int m0 = blockIdx.y * 64, n0 = blockIdx.x * 128;
    gemm_wmma3<false, true>(g_xh + (size_t)m0 * 512, g_xl + (size_t)m0 * 512, 512,
                            g_wqh + (size_t)n0 * 512, g_wql + (size_t)n0 * 512, 512,
                            512, g_qkv + (size_t)m0 * 1536 + n0, 1536);
}

// ================= K4: Gram[b] = X^T X (A col-major view of x) =================
__global__ __launch_bounds__(128) void k_gram_w() {
    int b = blockIdx.z;
    int c10 = blockIdx.y * 64, c20 = blockIdx.x * 128;
    const __nv_bfloat16* xh = g_xh + (size_t)b * N_ * C_;
    const __nv_bfloat16* xl = g_xl + (size_t)b * N_ * C_;
    gemm_wmma3<true, false>(xh + c10, xl + c10, 512, xh + c20, xl + c20, 512,
                            N_, g_gram + ((size_t)(b * 512 + c10)) * 512 + c20, 512);
}

// ================= K8: out[:, :256] = xsa @ w_o1^T =================
__global__ __launch_bounds__(128) void k_out1_w(float* __restrict__ out) {
    int m0 = blockIdx.y * 64, n0 = blockIdx.x * 128;
    gemm_wmma3<false, true>(g_xsah + (size_t)m0 * 512, g_xsal + (size_t)m0 * 512, 512,
                            g_wo1h + (size_t)n0 * 512, g_wo1l + (size_t)n0 * 512, 512,
                            512, out + (size_t)m0 * 512 + n0, 512);
}

// ================= K9: out[:, 256:] = x @ M[b] =================
__global__ __launch_bounds__(128) void k_out2_w(float* __restrict__ out) {
    int m0 = blockIdx.y * 64, n0 = blockIdx.x * 128;
    int b = m0 >> 12;
    gemm_wmma3<false, true>(g_xh + (size_t)m0 * 512, g_xl + (size_t)m0 * 512, 512,
                            g_Mh + ((size_t)b * 256 + n0) * 512,
                            g_Ml + ((size_t)b * 256 + n0) * 512, 512,
                            512, out + (size_t)m0 * 512 + 256 + n0, 512);
}

// ================= K3: kp/vp via wmma, split-on-stage from fp32 =============
#define RSTR 40
#define KSTRA 72
__device__ __forceinline__ void pack4(float4 v, __nv_bfloat16* h, __nv_bfloat16* l) {
    __nv_bfloat16 hh[4], ll[4];
    split_bf16(v.x, hh[0], ll[0]); split_bf16(v.y, hh[1], ll[1]);
    split_bf16(v.z, hh[2], ll[2]); split_bf16(v.w, hh[3], ll[3]);
    *(uint2*)h = *(uint2*)hh;
    *(uint2*)l = *(uint2*)ll;
}

__global__ __launch_bounds__(128) void k_proj_w(const float* __restrict__ w_e,
                                                const float* __restrict__ b_e) {
    __shared__ __nv_bfloat16 sAh[64 * RSTR], sAl[64 * RSTR];   // w_e tile 64x32
    __shared__ __nv_bfloat16 sBh[32 * KSTRA], sBl[32 * KSTRA]; // KV tile 32x64
    int tid = threadIdx.x;
    int wn = tid >> 5;
    int h = blockIdx.x;
    int b = blockIdx.y >> 1, kv = blockIdx.y & 1;
    const float* Bp = g_qkv + (size_t)b * N_ * 1536 + 512 + kv * 512 + h * 64;

    float4 rA[4], rB[4];
    auto LD = [&](int k0) {
#pragma unroll
        for (int u = 0; u < 4; u++) {
            int idx = u * 128 + tid;
            int rowA = idx >> 3, qA = idx & 7;
            rA[u] = *(const float4*)&w_e[(size_t)rowA * N_ + k0 + qA * 4];
            int krB = idx >> 4, qB = idx & 15;
            rB[u] = *(const float4*)&Bp[(size_t)(k0 + krB) * 1536 + qB * 4];
        }
    };
    auto ST = [&]() {
#pragma unroll
        for (int u = 0; u < 4; u++) {
            int idx = u * 128 + tid;
            int rowA = idx >> 3, qA = idx & 7;
            pack4(rA[u], sAh + rowA * RSTR + qA * 4, sAl + rowA * RSTR + qA * 4);
            int krB = idx >> 4, qB = idx & 15;
            pack4(rB[u], sBh + krB * KSTRA + qB * 4, sBl + krB * KSTRA + qB * 4);
        }
    };

    wmma::fragment<wmma::accumulator, 16, 16, 16, float> acc[4];
#pragma unroll
    for (int i = 0; i < 4; i++) wmma::fill_fragment(acc[i], 0.0f);

    LD(0); ST();
    __syncthreads();

    int nk = N_ >> 5;
    for (int kt = 0; kt < nk; kt++) {
        if (kt + 1 < nk) LD((kt + 1) << 5);
#pragma unroll
        for (int kk = 0; kk < 32; kk += 16) {
            wmma::fragment<wmma::matrix_a, 16, 16, 16, __nv_bfloat16, wmma::row_major> ah[4], al[4];
            wmma::fragment<wmma::matrix_b, 16, 16, 16, __nv_bfloat16, wmma::row_major> bh, bl;
#pragma unroll
            for (int i = 0; i < 4; i++) {
                wmma::load_matrix_sync(ah[i], sAh + i * 16 * RSTR + kk, RSTR);
                wmma::load_matrix_sync(al[i], sAl + i * 16 * RSTR + kk, RSTR);
            }
            wmma::load_matrix_sync(bh, sBh + kk * KSTRA + wn * 16, KSTRA);
            wmma::load_matrix_sync(bl, sBl + kk * KSTRA + wn * 16, KSTRA);
#pragma unroll
            for (int i = 0; i < 4; i++) {
                wmma::mma_sync(acc[i], ah[i], bh, acc[i]);
                wmma::mma_sync(acc[i], ah[i], bl, acc[i]);
                wmma::mma_sync(acc[i], al[i], bh, acc[i]);
            }
        }
        if (kt + 1 < nk) {
            __syncthreads();
            ST();
            __syncthreads();
        }
    }
    float* dst = (kv ? g_vp : g_kp) + (size_t)(b * 8 + h) * (P_ * D_);
#pragma unroll
    for (int i = 0; i < 4; i++)
        wmma::store_matrix_sync(dst + i * 16 * 64 + wn * 16, acc[i], 64,
                                wmma::mem_row_major);
    __syncthreads();
    for (int idx = tid; idx < P_ * D_; idx += 128) dst[idx] += b_e[idx >> 6];
}

// ================= bias epilogue: out[r][c] += b_o1/b_o2 =================
__global__ __launch_bounds__(256) void k_bias(const float* __restrict__ b_o1,
                                              const float* __restrict__ b_o2,
                                              float* __restrict__ out) {
    size_t i = ((size_t)blockIdx.x * 256 + threadIdx.x) * 4;
    int c = (int)(i & 511);
    const float* bias = (c < 256) ? (b_o1 + c) : (b_o2 + c - 256);
    float4 v = *(float4*)(out + i);
    float4 bb = *(const float4*)bias;
    v.x += bb.x; v.y += bb.y; v.z += bb.z; v.w += bb.w;
    *(float4*)(out + i) = v;
}

// ================= conversions (destinations referenced in DEVICE code) =====
__device__ __forceinline__ void split4_to(const float* __restrict__ s,
                                          __nv_bfloat16* __restrict__ h,
                                          __nv_bfloat16* __restrict__ l, size_t i) {
    float4 v = *(const float4*)(s + i);
    __nv_bfloat16 hh[4], ll[4];
    split_bf16(v.x, hh[0], ll[0]); split_bf16(v.y, hh[1], ll[1]);
    split_bf16(v.z, hh[2], ll[2]); split_bf16(v.w, hh[3], ll[3]);
    *(uint2*)(h + i) = *(uint2*)hh;
    *(uint2*)(l + i) = *(uint2*)ll;
}

__global__ void c_split_x(const float* __restrict__ s) {
    size_t i = ((size_t)blockIdx.x * 256 + threadIdx.x) * 4;
    split4_to(s, g_xh, g_xl, i);
}
__global__ void c_split_wq(const float* __restrict__ s) {
    size_t i = ((size_t)blockIdx.x * 256 + threadIdx.x) * 4;
    split4_to(s, g_wqh, g_wql, i);
}
__global__ void c_split_wo1(const float* __restrict__ s) {
    size_t i = ((size_t)blockIdx.x * 256 + threadIdx.x) * 4;
    split4_to(s, g_wo1h, g_wo1l, i);
}

// ================= K2: q token-axis L2 norm inverses =================
__global__ __launch_bounds__(256) void k_qnorm() {
    int bh = blockIdx.x;
    int b = bh >> 3, h = bh & 7;
    int tid = threadIdx.x;
    int d = tid & 63, sl = tid >> 6;
    const float* q = g_qkv + (size_t)b * (N_ * 1536) + h * 64 + d;
    float s = 0.f;
    for (int n = sl; n < N_; n += 4) {
        float v = q[(size_t)n * 1536];
        s += v * v;
    }
    __shared__ float red[256];
    red[tid] = s;
    __syncthreads();
    if (sl == 0) {
        float tot = red[d] + red[d + 64] + red[d + 128] + red[d + 192];
        g_qinv[bh * 64 + d] = 1.f / fmaxf(sqrtf(tot), 1e-12f);
    }
}

// ================= K5: row softmax of Gram * temperature =================
__global__ __launch_bounds__(256) void k_softmax512(const float* __restrict__ temp) {
    int row = blockIdx.x;
    float t = temp[0];
    float* p = g_gram + (size_t)row * 512;
    int tid = threadIdx.x;
    __shared__ float red[256];
    float v0 = p[tid] * t, v1 = p[tid + 256] * t;
    red[tid] = fmaxf(v0, v1);
    __syncthreads();
    for (int s = 128; s > 0; s >>= 1) {
        if (tid < s) red[tid] = fmaxf(red[tid], red[tid + s]);
        __syncthreads();
    }
    float mx = red[0];
    __syncthreads();
    float e0 = __expf(v0 - mx), e1 = __expf(v1 - mx);
    red[tid] = e0 + e1;
    __syncthreads();
    for (int s = 128; s > 0; s >>= 1) {
        if (tid < s) red[tid] += red[tid + s];
        __syncthreads();
    }
    float inv = 1.f / red[0];
    p[tid] = e0 * inv;
    p[tid + 256] = e1 * inv;
}

// ================= K6: fused spatial attention (writes bf16 hi/lo) =================
__global__ __launch_bounds__(128) void k_sa(const float* __restrict__ temp2) {
    __shared__ float kp_s[P_ * D_];
    __shared__ float vp_s[P_ * D_];
    __shared__ float qi_s[D_];
    int bh = blockIdx.y;
    int b = bh >> 3, h = bh & 7;
    int n = blockIdx.x * 128 + threadIdx.x;
    const float4* kp4 = (const float4*)(g_kp + bh * (P_ * D_));
    const float4* vp4 = (const float4*)(g_vp + bh * (P_ * D_));
    for (int i = threadIdx.x; i < (P_ * D_) / 4; i += 128) {
        ((float4*)kp_s)[i] = kp4[i];
        ((float4*)vp_s)[i] = vp4[i];
    }
    if (threadIdx.x < 64) qi_s[threadIdx.x] = g_qinv[bh * 64 + threadIdx.x];
    __syncthreads();
    float t2 = temp2[h];
    const float* qrow = g_qkv + (size_t)b * (N_ * 1536) + (size_t)n * 1536 + h * 64;

    float q[64];
#pragma unroll
    for (int d = 0; d < 64; d++) q[d] = qrow[d] * qi_s[d];

    float s[64];
    float mx = -1e30f;
#pragma unroll
    for (int p = 0; p < 64; p++) {
        float acc = 0.f;
#pragma unroll
        for (int d = 0; d < 64; d += 4) {
            float4 k4 = *(const float4*)&kp_s[p * 64 + d];
            acc += q[d] * k4.x + q[d + 1] * k4.y + q[d + 2] * k4.z + q[d + 3] * k4.w;
        }
        s[p] = acc * t2;
        mx = fmaxf(mx, s[p]);
    }
    float sum = 0.f;
#pragma unroll
    for (int p = 0; p < 64; p++) {
        s[p] = __expf(s[p] - mx);
        sum += s[p];
    }
    float inv = 1.f / sum;

    float o[64];
#pragma unroll
    for (int d = 0; d < 64; d++) o[d] = 0.f;
#pragma unroll
    for (int p = 0; p < 64; p++) {
        float sp = s[p] * inv;
#pragma unroll
        for (int d = 0; d < 64; d += 4) {
            float4 v4 = *(const float4*)&vp_s[p * 64 + d];
            o[d] += sp * v4.x;
            o[d + 1] += sp * v4.y;
            o[d + 2] += sp * v4.z;
            o[d + 3] += sp * v4.w;
        }
    }
    int rbase = h * 8 + (n >> 9);
    int col = n & 511;
    size_t boff = (size_t)b * (N_ * C_);
#pragma unroll
    for (int d = 0; d < 64; d++) {
        __nv_bfloat16 hh, ll;
        split_bf16(o[d], hh, ll);
        size_t idx = boff + (size_t)(d * 64 + rbase) * 512 + col;
        g_xsah[idx] = hh;
        g_xsal[idx] = ll;
    }
}

// ================= K7: M^T[b,j,k] = (attn^T @ w_o2^T)^T, bf16 hi/lo out =================
#define SP2 132
template <bool AT, bool BT>
__device__ __forceinline__ void gemm128x128(
    const float* __restrict__ A, int lda, const float* __restrict__ B, int ldb,
    int K, float (&acc)[8][8], float (*As)[8][SP2], float (*Bs)[8][SP2]) {
    int tid = threadIdx.x;
    int tx = tid & 15, ty = tid >> 4;
    int rowT = tid >> 1, kqT = (tid & 1) * 4;
    int krD = tid >> 5, mqD = (tid & 31) * 4;
    float4 ra, rb;
    auto loadA = [&](int k0) {
        if (AT) ra = *(const float4*)&A[(size_t)rowT * lda + k0 + kqT];
        else    ra = *(const float4*)&A[(size_t)(k0 + krD) * lda + mqD];
    };
    auto loadB = [&](int k0) {
        if (BT) rb = *(const float4*)&B[(size_t)rowT * ldb + k0 + kqT];
        else    rb = *(const float4*)&B[(size_t)(k0 + krD) * ldb + mqD];
    };
    auto storeA = [&](int buf) {
        if (AT) {
            As[buf][kqT + 0][rowT] = ra.x; As[buf][kqT + 1][rowT] = ra.y;
            As[buf][kqT + 2][rowT] = ra.z; As[buf][kqT + 3][rowT] = ra.w;
        } else *(float4*)&As[buf][krD][mqD] = ra;
    };
    auto storeB = [&](int buf) {
        if (BT) {
            Bs[buf][kqT + 0][rowT] = rb.x; Bs[buf][kqT + 1][rowT] = rb.y;
            Bs[buf][kqT + 2][rowT] = rb.z; Bs[buf][kqT + 3][rowT] = rb.w;
        } else *(float4*)&Bs[buf][krD][mqD] = rb;
    };
    loadA(0); loadB(0); storeA(0); storeB(0);
    __syncthreads();
    int nk = K >> 3;
    for (int kt = 0; kt < nk; kt++) {
        int cur = kt & 1;
        if (kt + 1 < nk) { loadA((kt + 1) << 3); loadB((kt + 1) << 3); }
#pragma unroll
        for (int kk = 0; kk < 8; kk++) {
            float4 a0 = *(const float4*)&As[cur][kk][ty * 8];
            float4 a1 = *(const float4*)&As[cur][kk][ty * 8 + 4];
            float4 b0 = *(const float4*)&Bs[cur][kk][tx * 8];
            float4 b1 = *(const float4*)&Bs[cur][kk][tx * 8 + 4];
            float a[8] = {a0.x, a0.y, a0.z, a0.w, a1.x, a1.y, a1.z, a1.w};
            float b[8] = {b0.x, b0.y, b0.z, b0.w, b1.x, b1.y, b1.z, b1.w};
#pragma unroll
            for (int i = 0; i < 8; i++)
#pragma unroll
                for (int j = 0; j < 8; j++) acc[i][j] += a[i] * b[j];
        }
        if (kt + 1 < nk) { storeA(cur ^ 1); storeB(cur ^ 1); __syncthreads(); }
    }
}

__global__ __launch_bounds__(256) void k_M(const float* __restrict__ w_o2) {
    __shared__ float As[2][8][SP2];
    __shared__ float Bs[2][8][SP2];
    int b = blockIdx.z;
    int m0 = blockIdx.y * 128;  // c'
    int n0 = blockIdx.x * 128;  // j (only 2 tiles: 256 cols)
    const float* A = g_gram + (size_t)b * (512 * 512);
    float acc[8][8] = {};
    gemm128x128<false, true>(A + m0, 512, w_o2 + (size_t)n0 * 512, 512, 512, acc, As, Bs);
    int tx = threadIdx.x & 15, ty = threadIdx.x >> 4;
#pragma unroll
    for (int i = 0; i < 8; i++) {
        int k = m0 + ty * 8 + i;
#pragma unroll
        for (int jj = 0; jj < 8; jj++) {
            int j = n0 + tx * 8 + jj;
            __nv_bfloat16 hh, ll;
            split_bf16(acc[i][jj], hh, ll);
            size_t idx = ((size_t)b * 256 + j) * 512 + k;
            g_Mh[idx] = hh;
            g_Ml[idx] = ll;
        }
    }
}

// ================= launch =================
extern "C" void kernel_launch(void* const* d_in, const int* in_sizes, int n_in,
                              void* d_out, int out_size) {
    const float* x      = (const float*)d_in[0];
    const float* w_qkv  = (const float*)d_in[1];
    const float* w_e    = (const float*)d_in[2];
    const float* b_e    = (const float*)d_in[3];
    const float* temp   = (const float*)d_in[4];
    const float* temp2  = (const float*)d_in[5];
    const float* w_o1   = (const float*)d_in[6];
    const float* b_o1   = (const float*)d_in[7];
    const float* w_o2   = (const float*)d_in[8];
    const float* b_o2   = (const float*)d_in[9];
    float* out = (float*)d_out;

    // bf16 hi/lo conversions (globals referenced inside kernels only)
    c_split_x<<<(B_ * N_ * C_) / 1024, 256>>>(x);
    c_split_wq<<<(3 * C_ * C_) / 1024, 256>>>(w_qkv);
    c_split_wo1<<<((C_ / 2) * C_) / 1024, 256>>>(w_o1);

    k_qkv_w<<<dim3(12, 512), 128>>>();            // 51.5 GF (x3 passes)
    k_qnorm<<<64, 256>>>();
    k_proj_w<<<dim3(8, 16), 128>>>(w_e, b_e);     // wmma, split-on-stage
    k_gram_w<<<dim3(4, 8, 8), 128>>>();           // 17.2 GF
    k_softmax512<<<B_ * C_, 256>>>(temp);
    k_sa<<<dim3(32, 64), 128>>>(temp2);
    k_M<<<dim3(2, 4, 8), 256>>>(w_o2);            // j has 2 tiles (256 cols)
    k_out1_w<<<dim3(2, 512), 128>>>(out);         // 8.6 GF
    k_out2_w<<<dim3(2, 512), 128>>>(out);         // 8.6 GF
    k_bias<<<(B_ * N_ * C_) / 1024, 256>>>(b_o1, b_o2, out);
}